// round 9
// baseline (speedup 1.0000x reference)
#include <cuda_runtime.h>
#include <cuda_bf16.h>
#include <cuda_fp16.h>
#include <math.h>
#include <stdint.h>

#define B_   4
#define T_   4096
#define H_   1024
#define S_   64
#define M_   (B_*T_)     // 16384 rows
#define NCH  64
#define TC   64
#define LN_EPSF 1e-5f

// ---- scratch ----
__device__ float g_u[M_*S_];
__device__ float g_L[B_*NCH*S_];
__device__ float g_E[B_*NCH*S_];
__device__ float g_states[M_*S_];
__device__ __half g_hn_hi[(size_t)M_*H_];          // 32 MB
__device__ __half g_wo_hi[(size_t)H_*H_];          // 2 MB
__device__ __half g_xh_hi[(size_t)M_*H_];          // 32 MB (fp16 hi of x)
__device__ __half g_xh_lo[(size_t)M_*H_];          // 32 MB (fp16 lo of x)
__device__ __half g_wgb_h[128*H_];                 // fp16 [2s]=Wg[s], [2s+1]=WB[s]
__device__ float2 g_wcp[(H_/2)*S_];                // WC packed col-pairwise (512 KB)

// ============================================================
// PTX helpers
// ============================================================
__device__ __forceinline__ uint32_t smem_u32(const void* p) {
    uint32_t a;
    asm("{ .reg .u64 t; cvta.to.shared.u64 t, %1; cvt.u32.u64 %0, t; }" : "=r"(a) : "l"(p));
    return a;
}
#define CP_ASYNC16(dst, src) \
    asm volatile("cp.async.cg.shared.global [%0], [%1], 16;" :: "r"(dst), "l"(src) : "memory")
#define CP_COMMIT() asm volatile("cp.async.commit_group;" ::: "memory")
#define CP_WAIT0()  asm volatile("cp.async.wait_group 0;" ::: "memory")

#define LDMX4(r, addr) \
    asm volatile("ldmatrix.sync.aligned.m8n8.x4.shared.b16 {%0,%1,%2,%3}, [%4];" \
        : "=r"((r)[0]), "=r"((r)[1]), "=r"((r)[2]), "=r"((r)[3]) : "r"(addr))

#define MMA_F16(c, a, b0v, b1v) \
    asm volatile("mma.sync.aligned.m16n8k16.row.col.f32.f16.f16.f32 " \
        "{%0,%1,%2,%3},{%4,%5,%6,%7},{%8,%9},{%0,%1,%2,%3};" \
        : "+f"((c)[0]), "+f"((c)[1]), "+f"((c)[2]), "+f"((c)[3]) \
        : "r"((a)[0]), "r"((a)[1]), "r"((a)[2]), "r"((a)[3]), "r"(b0v), "r"(b1v))

__device__ __forceinline__ unsigned long long fma2(unsigned long long a,
                                                   unsigned long long b,
                                                   unsigned long long c) {
    unsigned long long d;
    asm("fma.rn.f32x2 %0, %1, %2, %3;" : "=l"(d) : "l"(a), "l"(b), "l"(c));
    return d;
}

// ============================================================
// prep kernels
// ============================================================
__global__ void __launch_bounds__(256) xSplitH(const float* __restrict__ x) {
    const size_t base = (size_t)blockIdx.x * 1024 + threadIdx.x * 4;
    float4 v = *(const float4*)&x[base];
    float vv[4] = {v.x, v.y, v.z, v.w};
    #pragma unroll
    for (int t = 0; t < 4; t++) {
        __half hi = __float2half_rn(vv[t]);
        g_xh_hi[base + t] = hi;
        g_xh_lo[base + t] = __float2half_rn(vv[t] - __half2float(hi));
    }
}

__global__ void __launch_bounds__(256) wSplit(const float* __restrict__ Wout) {
    const int base = (blockIdx.x * 256 + threadIdx.x) * 4;
    #pragma unroll
    for (int t = 0; t < 4; t++)
        g_wo_hi[base + t] = __float2half_rn(Wout[base + t]);
}

__global__ void __launch_bounds__(256) wgbHalf(const float* __restrict__ Wg,
                                               const float* __restrict__ WB) {
    const int r = blockIdx.x;                     // packed row 0..127
    const int s = r >> 1;
    const float* src = (r & 1) ? &WB[(size_t)s * H_] : &Wg[(size_t)s * H_];
    for (int k = threadIdx.x * 4; k < H_; k += 1024) {
        #pragma unroll
        for (int t = 0; t < 4; t++)
            g_wgb_h[(size_t)r * H_ + k + t] = __float2half_rn(src[k + t]);
    }
}

__global__ void __launch_bounds__(64) wcPack(const float* __restrict__ WC) {
    const int p = blockIdx.x;                     // column pair 0..511
    const int k = threadIdx.x;                    // 0..63
    g_wcp[p * S_ + k] = make_float2(WC[(size_t)(2 * p) * S_ + k],
                                    WC[(size_t)(2 * p + 1) * S_ + k]);
}

// ============================================================
// shared GEMM geometry
// ============================================================
#define KT     64
#define SROW_B 144           // bytes per smem row (72 x b16)
#define STILE  (128*SROW_B)  // 18432 (128-row tile)
#define SMEM_D (4*STILE)     // 73728

// ============================================================
// Kernel A: u via fp16 2-seg MMA, MT=64 tile (grid 256).
// segs: A = x_hi(fp16) then x_lo(fp16); B = wgb fp16. K' = 2048.
// ============================================================
#define UA_TILE (64*SROW_B)              // 9216
#define UB_TILE (128*SROW_B)             // 18432
#define U_STAGE (UA_TILE + UB_TILE)      // 27648
#define SMEM_U  (2*U_STAGE)              // 55296

__global__ void __launch_bounds__(256, 2) uGemmMMA(const float* __restrict__ bg) {
    extern __shared__ char sm[];
    const uint32_t smb = smem_u32(sm);
    const int tid = threadIdx.x;
    const int lane = tid & 31, w = tid >> 5;
    const int wr = w >> 2, wc = w & 3;            // 2 x 4 warps; warp tile 32x32
    const int rowBase = blockIdx.x * 64;

    auto loadStage = [&](int stage, int it) {
        const int seg = it >> 4;                  // 0,1
        const int k0  = (it & 15) * KT;
        const __half* Asrc = seg ? g_xh_lo : g_xh_hi;
        const uint32_t aB = smb + stage * U_STAGE;
        const uint32_t bB = aB + UA_TILE;
        #pragma unroll
        for (int t = 0; t < 2; t++) {
            const int c = tid + t * 256;
            const int r = c >> 3, j = c & 7;
            CP_ASYNC16(aB + r * SROW_B + j * 16, &Asrc[(size_t)(rowBase + r) * H_ + k0 + j * 8]);
        }
        #pragma unroll
        for (int t = 0; t < 4; t++) {
            const int c = tid + t * 256;
            const int r = c >> 3, j = c & 7;
            CP_ASYNC16(bB + r * SROW_B + j * 16, &g_wgb_h[(size_t)r * H_ + k0 + j * 8]);
        }
        CP_COMMIT();
    };

    float acc[2][4][4];
    #pragma unroll
    for (int i = 0; i < 2; i++)
        #pragma unroll
        for (int j = 0; j < 4; j++)
            #pragma unroll
            for (int q = 0; q < 4; q++) acc[i][j][q] = 0.0f;

    loadStage(0, 0);
    const int NIT = 32;
    for (int it = 0; it < NIT; it++) {
        const int stage = it & 1;
        CP_WAIT0();
        __syncthreads();
        if (it + 1 < NIT) loadStage(stage ^ 1, it + 1);
        const uint32_t aT = smb + stage * U_STAGE;
        const uint32_t bT = aT + UA_TILE;
        #pragma unroll
        for (int ks = 0; ks < 4; ks++) {
            const int kb = ks * 32;
            uint32_t af[2][4];
            #pragma unroll
            for (int mi = 0; mi < 2; mi++) {
                const uint32_t addr = aT + (uint32_t)(wr * 32 + mi * 16 + (lane & 15)) * SROW_B
                                      + kb + ((lane >> 4) << 4);
                LDMX4(af[mi], addr);
            }
            uint32_t bf[2][4];
            #pragma unroll
            for (int nj = 0; nj < 2; nj++) {
                const uint32_t addr = bT + (uint32_t)(wc * 32 + nj * 16 + (lane & 15)) * SROW_B
                                      + kb + ((lane >> 4) << 4);
                LDMX4(bf[nj], addr);
            }
            #pragma unroll
            for (int mi = 0; mi < 2; mi++)
                #pragma unroll
                for (int ni = 0; ni < 4; ni++)
                    MMA_F16(acc[mi][ni], af[mi], bf[ni >> 1][ni & 1], bf[ni >> 1][(ni & 1) + 2]);
        }
        __syncthreads();
    }

    #pragma unroll
    for (int mi = 0; mi < 2; mi++) {
        const int r0 = rowBase + wr * 32 + mi * 16 + (lane >> 2);
        #pragma unroll
        for (int ni = 0; ni < 4; ni++) {
            const int c = wc * 32 + ni * 8 + (lane & 3) * 2;
            const int s = c >> 1;
            const float bgs = bg[s];
            float gate0 = 1.0f / (1.0f + expf(-(acc[mi][ni][0] + bgs)));
            float gate1 = 1.0f / (1.0f + expf(-(acc[mi][ni][2] + bgs)));
            g_u[(size_t)r0 * S_ + s]       = gate0 * acc[mi][ni][1];
            g_u[(size_t)(r0 + 8) * S_ + s] = gate1 * acc[mi][ni][3];
        }
    }
}

// ============================================================
// Scan kernels — batch loads into regs, then serial reg-only chain
// ============================================================
__global__ void scanLocal(const float* __restrict__ A_log) {
    const int b = blockIdx.x / NCH, c = blockIdx.x % NCH;
    const int s = threadIdx.x;
    const float a = expf(A_log[s]);
    const float* up = &g_u[((size_t)(b * T_) + c * TC) * S_ + s];
    float U[TC];
    #pragma unroll
    for (int i = 0; i < TC; i++) U[i] = up[i * S_];
    float st = 0.0f;
    #pragma unroll
    for (int i = 0; i < TC; i++) st = fmaf(a, st, U[i]);
    g_L[((size_t)b * NCH + c) * S_ + s] = st;
}

__global__ void scanCarry(const float* __restrict__ A_log, float* __restrict__ finalState) {
    const int tid = threadIdx.x;
    const int b = tid / S_, s = tid % S_;
    const float a = expf(A_log[s]);
    float aTC = 1.0f;
    #pragma unroll
    for (int i = 0; i < TC; i++) aTC *= a;
    float L[NCH];
    #pragma unroll
    for (int c = 0; c < NCH; c++)
        L[c] = g_L[((size_t)b * NCH + c) * S_ + s];
    float E = 0.0f;
    #pragma unroll
    for (int c = 0; c < NCH; c++) {
        g_E[((size_t)b * NCH + c) * S_ + s] = E;
        E = fmaf(aTC, E, L[c]);
    }
    if (finalState) finalState[b * S_ + s] = E;
}

__global__ void scanStates(const float* __restrict__ A_log) {
    const int b = blockIdx.x / NCH, c = blockIdx.x % NCH;
    const int s = threadIdx.x;
    const float a = expf(A_log[s]);
    const size_t base = ((size_t)(b * T_) + c * TC) * S_ + s;
    float U[TC];
    #pragma unroll
    for (int i = 0; i < TC; i++) U[i] = g_u[base + (size_t)i * S_];
    float st = g_E[((size_t)b * NCH + c) * S_ + s];
    #pragma unroll
    for (int i = 0; i < TC; i++) {
        st = fmaf(a, st, U[i]);
        g_states[base + (size_t)i * S_] = st;
    }
}

// ============================================================
// Kernel C: tiled yLN with packed f32x2 inner product.
// 16 rows/block, 512 threads; thread owns col pair (2t, 2t+1) x 16 rows.
// states duplicated in smem as (v,v); WC pre-packed col-pairwise.
// ============================================================
__global__ void __launch_bounds__(512) yLNT(const float* __restrict__ x,
                                            const float* __restrict__ Dv,
                                            const float* __restrict__ gamma,
                                            const float* __restrict__ beta) {
    __shared__ float2 st2[16][64];               // (v,v) duplicated
    __shared__ float redS[16][16], redQ[16][16];
    __shared__ float muA[16], invA[16];
    const int tid = threadIdx.x;
    const int lane = tid & 31, w = tid >> 5;
    const int rowBase = blockIdx.x * 16;
    const int p = tid;                            // col pair index
    const int c0 = p * 2;

    {   // load 16x64 states, duplicate
        const int r = tid >> 5, s0 = (tid & 31) * 2;
        float2 v = *(const float2*)&g_states[(size_t)(rowBase + r) * S_ + s0];
        st2[r][s0]     = make_float2(v.x, v.x);
        st2[r][s0 + 1] = make_float2(v.y, v.y);
    }
    __syncthreads();

    unsigned long long acc2[16];
    #pragma unroll
    for (int r = 0; r < 16; r++) acc2[r] = 0ULL;

    const float2* wrow = &g_wcp[(size_t)p * S_];
    #pragma unroll 2
    for (int s4 = 0; s4 < 16; s4++) {
        const int k = s4 * 4;
        ulonglong2 wA = *(const ulonglong2*)&wrow[k];       // pairs k, k+1
        ulonglong2 wB = *(const ulonglong2*)&wrow[k + 2];   // pairs k+2, k+3
        #pragma unroll
        for (int r = 0; r < 16; r++) {
            const unsigned long long* sv = (const unsigned long long*)&st2[r][k];
            acc2[r] = fma2(sv[0], wA.x, acc2[r]);
            acc2[r] = fma2(sv[1], wA.y, acc2[r]);
            acc2[r] = fma2(sv[2], wB.x, acc2[r]);
            acc2[r] = fma2(sv[3], wB.y, acc2[r]);
        }
    }

    float acc0[16], acc1[16];
    const float d0 = Dv[c0] + 1.0f, d1 = Dv[c0 + 1] + 1.0f;
    #pragma unroll
    for (int r = 0; r < 16; r++) {
        float2 yv = *(float2*)&acc2[r];
        float2 xv = *(const float2*)&x[(size_t)(rowBase + r) * H_ + c0];
        float h0 = fmaf(d0, xv.x, yv.x);
        float h1 = fmaf(d1, xv.y, yv.y);
        acc0[r] = h0; acc1[r] = h1;
        float sm = h0 + h1;
        float sq = fmaf(h0, h0, h1 * h1);
        #pragma unroll
        for (int o = 16; o > 0; o >>= 1) {
            sm += __shfl_down_sync(0xffffffffu, sm, o);
            sq += __shfl_down_sync(0xffffffffu, sq, o);
        }
        if (lane == 0) { redS[w][r] = sm; redQ[w][r] = sq; }
    }
    __syncthreads();
    if (tid < 16) {
        float s = 0.0f, q = 0.0f;
        #pragma unroll
        for (int i = 0; i < 16; i++) { s += redS[i][tid]; q += redQ[i][tid]; }
        float mu = s * (1.0f / H_);
        float var = q * (1.0f / H_) - mu * mu;
        muA[tid] = mu;
        invA[tid] = rsqrtf(var + LN_EPSF);
    }
    __syncthreads();

    const float g0 = gamma[c0], g1 = gamma[c0 + 1];
    const float b0 = beta[c0],  b1 = beta[c0 + 1];
    #pragma unroll
    for (int r = 0; r < 16; r++) {
        const float mu = muA[r], inv = invA[r];
        float v0 = fmaf((acc0[r] - mu) * inv, g0, b0);
        float v1 = fmaf((acc1[r] - mu) * inv, g1, b1);
        const size_t off = (size_t)(rowBase + r) * H_ + c0;
        *(__half2*)&g_hn_hi[off] = __halves2half2(__float2half_rn(v0), __float2half_rn(v1));
    }
}

// ============================================================
// Kernel D: out = hn_hi @ wo_hi^T + bout, 1-seg fp16 MMA (K = 1024)
// ============================================================
__global__ void __launch_bounds__(256, 2) outGemmMMA(const float* __restrict__ bout,
                                                     float* __restrict__ out) {
    extern __shared__ char sm[];
    const uint32_t smb = smem_u32(sm);
    const int tid = threadIdx.x;
    const int lane = tid & 31, w = tid >> 5;
    const int wr = w >> 2, wc = w & 3;
    const int rowBase = blockIdx.x * 128;
    const int colBase = blockIdx.y * 128;

    auto loadStage = [&](int stage, int it) {
        const int k0  = it * KT;
        const uint32_t aB = smb + stage * 2 * STILE;
        const uint32_t bB = aB + STILE;
        #pragma unroll
        for (int t = 0; t < 4; t++) {
            const int c = tid + t * 256;
            const int r = c >> 3, j = c & 7;
            CP_ASYNC16(aB + r * SROW_B + j * 16, &g_hn_hi[(size_t)(rowBase + r) * H_ + k0 + j * 8]);
            CP_ASYNC16(bB + r * SROW_B + j * 16, &g_wo_hi[(size_t)(colBase + r) * H_ + k0 + j * 8]);
        }
        CP_COMMIT();
    };

    float acc[4][4][4];
    #pragma unroll
    for (int i = 0; i < 4; i++)
        #pragma unroll
        for (int j = 0; j < 4; j++)
            #pragma unroll
            for (int q = 0; q < 4; q++) acc[i][j][q] = 0.0f;

    loadStage(0, 0);
    const int NIT = 16;
    for (int it = 0; it < NIT; it++) {
        const int stage = it & 1;
        CP_WAIT0();
        __syncthreads();
        if (it + 1 < NIT) loadStage(stage ^ 1, it + 1);
        const uint32_t aT = smb + stage * 2 * STILE;
        const uint32_t bT = aT + STILE;
        #pragma unroll
        for (int ks = 0; ks < 4; ks++) {
            const int kb = ks * 32;
            uint32_t af[4][4];
            #pragma unroll
            for (int mi = 0; mi < 4; mi++) {
                const uint32_t addr = aT + (uint32_t)(wr * 64 + mi * 16 + (lane & 15)) * SROW_B
                                      + kb + ((lane >> 4) << 4);
                LDMX4(af[mi], addr);
            }
            uint32_t bf[2][4];
            #pragma unroll
            for (int nj = 0; nj < 2; nj++) {
                const uint32_t addr = bT + (uint32_t)(wc * 32 + nj * 16 + (lane & 15)) * SROW_B
                                      + kb + ((lane >> 4) << 4);
                LDMX4(bf[nj], addr);
            }
            #pragma unroll
            for (int mi = 0; mi < 4; mi++)
                #pragma unroll
                for (int ni = 0; ni < 4; ni++)
                    MMA_F16(acc[mi][ni], af[mi], bf[ni >> 1][ni & 1], bf[ni >> 1][(ni & 1) + 2]);
        }
        __syncthreads();
    }

    #pragma unroll
    for (int mi = 0; mi < 4; mi++) {
        const int r0 = rowBase + wr * 64 + mi * 16 + (lane >> 2);
        #pragma unroll
        for (int ni = 0; ni < 4; ni++) {
            const int c = colBase + wc * 32 + ni * 8 + (lane & 3) * 2;
            const float b0c = bout[c], b1c = bout[c + 1];
            float2 v0 = make_float2(acc[mi][ni][0] + b0c, acc[mi][ni][1] + b1c);
            float2 v1 = make_float2(acc[mi][ni][2] + b0c, acc[mi][ni][3] + b1c);
            *(float2*)&out[(size_t)r0 * H_ + c]       = v0;
            *(float2*)&out[(size_t)(r0 + 8) * H_ + c] = v1;
        }
    }
}

// ============================================================
// launch
// ============================================================
extern "C" void kernel_launch(void* const* d_in, const int* in_sizes, int n_in,
                              void* d_out, int out_size) {
    const float* x     = (const float*)d_in[0];
    const float* A_log = (const float*)d_in[1];
    const float* WB    = (const float*)d_in[2];
    const float* WC    = (const float*)d_in[3];
    const float* Dv    = (const float*)d_in[4];
    const float* Wg    = (const float*)d_in[5];
    const float* bg    = (const float*)d_in[6];
    const float* Wout  = (const float*)d_in[7];
    const float* bout  = (const float*)d_in[8];
    const float* gamma = (const float*)d_in[9];
    const float* beta  = (const float*)d_in[10];

    float* out = (float*)d_out;
    float* finalState = (out_size >= M_ * H_ + B_ * S_) ? out + (size_t)M_ * H_ : nullptr;

    cudaFuncSetAttribute(outGemmMMA, cudaFuncAttributeMaxDynamicSharedMemorySize, SMEM_D);
    cudaFuncSetAttribute(uGemmMMA,   cudaFuncAttributeMaxDynamicSharedMemorySize, SMEM_U);

    wSplit<<<H_*H_/1024, 256>>>(Wout);
    wgbHalf<<<128, 256>>>(Wg, WB);
    wcPack<<<H_/2, 64>>>(WC);
    xSplitH<<<M_*H_/1024, 256>>>(x);
    uGemmMMA<<<M_/64, 256, SMEM_U>>>(bg);
    scanLocal<<<B_*NCH, S_>>>(A_log);
    scanCarry<<<1, B_*S_>>>(A_log, finalState);
    scanStates<<<B_*NCH, S_>>>(A_log);
    yLNT<<<M_/16, 512>>>(x, Dv, gamma, beta);
    dim3 gD(M_/128, H_/128);
    outGemmMMA<<<gD, 256, SMEM_D>>>(bout, out);
}

// round 10
// speedup vs baseline: 1.0448x; 1.0448x over previous
#include <cuda_runtime.h>
#include <cuda_bf16.h>
#include <cuda_fp16.h>
#include <math.h>
#include <stdint.h>

#define B_   4
#define T_   4096
#define H_   1024
#define S_   64
#define M_   (B_*T_)     // 16384 rows
#define NCH  64
#define TC   64
#define LN_EPSF 1e-5f

// ---- scratch ----
__device__ float g_E[B_*NCH*S_];                   // entering state per chunk
__device__ float g_aPow[TC*S_];                    // a_s^(i+1), 16 KB
__device__ float g_u[M_*S_];
__device__ float g_states[M_*S_];                  // LOCAL states (corrected in yLNT)
__device__ __half g_hn_hi[(size_t)M_*H_];          // 32 MB
__device__ __half g_wo_hi[(size_t)H_*H_];          // 2 MB
__device__ __half g_xh_hi[(size_t)M_*H_];          // 32 MB (fp16 of x)
__device__ __half g_wgb_h[128*H_];                 // fp16 [2s]=Wg[s], [2s+1]=WB[s]
__device__ float2 g_wcp[(H_/2)*S_];                // WC packed col-pairwise (512 KB)

// ============================================================
// PTX helpers
// ============================================================
__device__ __forceinline__ uint32_t smem_u32(const void* p) {
    uint32_t a;
    asm("{ .reg .u64 t; cvta.to.shared.u64 t, %1; cvt.u32.u64 %0, t; }" : "=r"(a) : "l"(p));
    return a;
}
#define CP_ASYNC16(dst, src) \
    asm volatile("cp.async.cg.shared.global [%0], [%1], 16;" :: "r"(dst), "l"(src) : "memory")
#define CP_COMMIT() asm volatile("cp.async.commit_group;" ::: "memory")
#define CP_WAIT0()  asm volatile("cp.async.wait_group 0;" ::: "memory")

#define LDMX4(r, addr) \
    asm volatile("ldmatrix.sync.aligned.m8n8.x4.shared.b16 {%0,%1,%2,%3}, [%4];" \
        : "=r"((r)[0]), "=r"((r)[1]), "=r"((r)[2]), "=r"((r)[3]) : "r"(addr))

#define MMA_F16(c, a, b0v, b1v) \
    asm volatile("mma.sync.aligned.m16n8k16.row.col.f32.f16.f16.f32 " \
        "{%0,%1,%2,%3},{%4,%5,%6,%7},{%8,%9},{%0,%1,%2,%3};" \
        : "+f"((c)[0]), "+f"((c)[1]), "+f"((c)[2]), "+f"((c)[3]) \
        : "r"((a)[0]), "r"((a)[1]), "r"((a)[2]), "r"((a)[3]), "r"(b0v), "r"(b1v))

__device__ __forceinline__ unsigned long long fma2(unsigned long long a,
                                                   unsigned long long b,
                                                   unsigned long long c) {
    unsigned long long d;
    asm("fma.rn.f32x2 %0, %1, %2, %3;" : "=l"(d) : "l"(a), "l"(b), "l"(c));
    return d;
}

// ============================================================
// prep kernels
// ============================================================
__global__ void __launch_bounds__(256) xSplitH(const float* __restrict__ x) {
    const size_t base = (size_t)blockIdx.x * 1024 + threadIdx.x * 4;
    float4 v = *(const float4*)&x[base];
    __half2 h0 = __halves2half2(__float2half_rn(v.x), __float2half_rn(v.y));
    __half2 h1 = __halves2half2(__float2half_rn(v.z), __float2half_rn(v.w));
    *(__half2*)&g_xh_hi[base]     = h0;
    *(__half2*)&g_xh_hi[base + 2] = h1;
}

__global__ void __launch_bounds__(256) wSplit(const float* __restrict__ Wout) {
    const int base = (blockIdx.x * 256 + threadIdx.x) * 4;
    #pragma unroll
    for (int t = 0; t < 4; t++)
        g_wo_hi[base + t] = __float2half_rn(Wout[base + t]);
}

__global__ void __launch_bounds__(256) wgbHalf(const float* __restrict__ Wg,
                                               const float* __restrict__ WB) {
    const int r = blockIdx.x;                     // packed row 0..127
    const int s = r >> 1;
    const float* src = (r & 1) ? &WB[(size_t)s * H_] : &Wg[(size_t)s * H_];
    for (int k = threadIdx.x * 4; k < H_; k += 1024) {
        #pragma unroll
        for (int t = 0; t < 4; t++)
            g_wgb_h[(size_t)r * H_ + k + t] = __float2half_rn(src[k + t]);
    }
}

__global__ void __launch_bounds__(64) wcPack(const float* __restrict__ WC) {
    const int p = blockIdx.x;                     // column pair 0..511
    const int k = threadIdx.x;                    // 0..63
    g_wcp[p * S_ + k] = make_float2(WC[(size_t)(2 * p) * S_ + k],
                                    WC[(size_t)(2 * p + 1) * S_ + k]);
}

__global__ void __launch_bounds__(64) aPowK(const float* __restrict__ A_log) {
    const int s = threadIdx.x;
    const float a = expf(A_log[s]);
    float p = 1.0f;
    for (int i = 0; i < TC; i++) {
        p *= a;                                   // a^(i+1)
        g_aPow[i * S_ + s] = p;
    }
}

// ============================================================
// shared GEMM geometry
// ============================================================
#define KT     64
#define SROW_B 144           // bytes per smem row (72 x b16)
#define STILE  (128*SROW_B)  // 18432 (128-row tile)
#define SMEM_D (4*STILE)     // 73728

// ============================================================
// Kernel A: u via fp16 1-seg MMA, MT=64 tile (grid 256). K = 1024.
// ============================================================
#define UA_TILE (64*SROW_B)              // 9216
#define UB_TILE (128*SROW_B)             // 18432
#define U_STAGE (UA_TILE + UB_TILE)      // 27648
#define SMEM_U  (2*U_STAGE)              // 55296

__global__ void __launch_bounds__(256, 2) uGemmMMA(const float* __restrict__ bg) {
    extern __shared__ char sm[];
    const uint32_t smb = smem_u32(sm);
    const int tid = threadIdx.x;
    const int lane = tid & 31, w = tid >> 5;
    const int wr = w >> 2, wc = w & 3;            // 2 x 4 warps; warp tile 32x32
    const int rowBase = blockIdx.x * 64;

    auto loadStage = [&](int stage, int it) {
        const int k0  = it * KT;
        const uint32_t aB = smb + stage * U_STAGE;
        const uint32_t bB = aB + UA_TILE;
        #pragma unroll
        for (int t = 0; t < 2; t++) {
            const int c = tid + t * 256;
            const int r = c >> 3, j = c & 7;
            CP_ASYNC16(aB + r * SROW_B + j * 16, &g_xh_hi[(size_t)(rowBase + r) * H_ + k0 + j * 8]);
        }
        #pragma unroll
        for (int t = 0; t < 4; t++) {
            const int c = tid + t * 256;
            const int r = c >> 3, j = c & 7;
            CP_ASYNC16(bB + r * SROW_B + j * 16, &g_wgb_h[(size_t)r * H_ + k0 + j * 8]);
        }
        CP_COMMIT();
    };

    float acc[2][4][4];
    #pragma unroll
    for (int i = 0; i < 2; i++)
        #pragma unroll
        for (int j = 0; j < 4; j++)
            #pragma unroll
            for (int q = 0; q < 4; q++) acc[i][j][q] = 0.0f;

    loadStage(0, 0);
    const int NIT = 16;
    for (int it = 0; it < NIT; it++) {
        const int stage = it & 1;
        CP_WAIT0();
        __syncthreads();
        if (it + 1 < NIT) loadStage(stage ^ 1, it + 1);
        const uint32_t aT = smb + stage * U_STAGE;
        const uint32_t bT = aT + UA_TILE;
        #pragma unroll
        for (int ks = 0; ks < 4; ks++) {
            const int kb = ks * 32;
            uint32_t af[2][4];
            #pragma unroll
            for (int mi = 0; mi < 2; mi++) {
                const uint32_t addr = aT + (uint32_t)(wr * 32 + mi * 16 + (lane & 15)) * SROW_B
                                      + kb + ((lane >> 4) << 4);
                LDMX4(af[mi], addr);
            }
            uint32_t bf[2][4];
            #pragma unroll
            for (int nj = 0; nj < 2; nj++) {
                const uint32_t addr = bT + (uint32_t)(wc * 32 + nj * 16 + (lane & 15)) * SROW_B
                                      + kb + ((lane >> 4) << 4);
                LDMX4(bf[nj], addr);
            }
            #pragma unroll
            for (int mi = 0; mi < 2; mi++)
                #pragma unroll
                for (int ni = 0; ni < 4; ni++)
                    MMA_F16(acc[mi][ni], af[mi], bf[ni >> 1][ni & 1], bf[ni >> 1][(ni & 1) + 2]);
        }
        __syncthreads();
    }

    #pragma unroll
    for (int mi = 0; mi < 2; mi++) {
        const int r0 = rowBase + wr * 32 + mi * 16 + (lane >> 2);
        #pragma unroll
        for (int ni = 0; ni < 4; ni++) {
            const int c = wc * 32 + ni * 8 + (lane & 3) * 2;
            const int s = c >> 1;
            const float bgs = bg[s];
            float gate0 = 1.0f / (1.0f + expf(-(acc[mi][ni][0] + bgs)));
            float gate1 = 1.0f / (1.0f + expf(-(acc[mi][ni][2] + bgs)));
            g_u[(size_t)r0 * S_ + s]       = gate0 * acc[mi][ni][1];
            g_u[(size_t)(r0 + 8) * S_ + s] = gate1 * acc[mi][ni][3];
        }
    }
}

// ============================================================
// scanLS: one block per batch. Phase 1: local scan (E=0) writes LOCAL
// states to g_states AND chunk carries to smem. Phase 2: serial
// cross-chunk carry -> g_E + finalState. Correction happens in yLNT.
// thread = (chunk c = tid>>4, s-quad sv = tid&15 -> s0 = 4*sv), float4 lanes.
// ============================================================
__global__ void __launch_bounds__(1024) scanLS(const float* __restrict__ A_log,
                                               float* __restrict__ finalState) {
    __shared__ float4 Ls[NCH][16];
    const int b = blockIdx.x;
    const int tid = threadIdx.x;
    const int c = tid >> 4;
    const int sv = tid & 15;
    const int s0 = sv * 4;

    float4 av;
    av.x = expf(A_log[s0 + 0]); av.y = expf(A_log[s0 + 1]);
    av.z = expf(A_log[s0 + 2]); av.w = expf(A_log[s0 + 3]);

    const size_t base = ((size_t)b * T_ + c * TC) * S_ + s0;
    float4 st = make_float4(0.f, 0.f, 0.f, 0.f);
    #pragma unroll 8
    for (int i = 0; i < TC; i++) {
        float4 u = *(const float4*)&g_u[base + (size_t)i * S_];
        st.x = fmaf(av.x, st.x, u.x);
        st.y = fmaf(av.y, st.y, u.y);
        st.z = fmaf(av.z, st.z, u.z);
        st.w = fmaf(av.w, st.w, u.w);
        *(float4*)&g_states[base + (size_t)i * S_] = st;   // LOCAL state
    }
    Ls[c][sv] = st;
    __syncthreads();

    if (tid < S_) {
        const int s = tid;
        const float a = expf(A_log[s]);
        float aTC = 1.0f;
        #pragma unroll
        for (int i = 0; i < TC; i++) aTC *= a;
        float L[NCH];
        #pragma unroll
        for (int cc = 0; cc < NCH; cc++)
            L[cc] = ((const float*)&Ls[cc][s >> 2])[s & 3];
        float E = 0.0f;
        #pragma unroll
        for (int cc = 0; cc < NCH; cc++) {
            g_E[((size_t)b * NCH + cc) * S_ + s] = E;      // entering state
            E = fmaf(aTC, E, L[cc]);
        }
        if (finalState) finalState[b * S_ + s] = E;
    }
}

// ============================================================
// Kernel C: tiled yLN with packed f32x2 inner product + fused scan
// correction: states[i] = local[i] + aPow[i]*E.
// 16 rows/block (all in one chunk), 512 threads.
// ============================================================
__global__ void __launch_bounds__(512) yLNT(const float* __restrict__ x,
                                            const float* __restrict__ Dv,
                                            const float* __restrict__ gamma,
                                            const float* __restrict__ beta) {
    __shared__ float2 st2[16][64];               // (v,v) duplicated corrected states
    __shared__ float redS[16][16], redQ[16][16];
    __shared__ float muA[16], invA[16];
    const int tid = threadIdx.x;
    const int lane = tid & 31, w = tid >> 5;
    const int rowBase = blockIdx.x * 16;
    const int p = tid;                            // col pair index
    const int c0 = p * 2;

    {   // load 16x64 local states, apply entering-state correction, duplicate
        const int r = tid >> 5, s0 = (tid & 31) * 2;
        const int eRow = rowBase >> 6;            // global chunk index m/64
        const int i0 = rowBase & 63;              // step-in-chunk of row 0
        float2 loc = *(const float2*)&g_states[(size_t)(rowBase + r) * S_ + s0];
        float2 Ev  = *(const float2*)&g_E[(size_t)eRow * S_ + s0];
        float2 pw  = *(const float2*)&g_aPow[(i0 + r) * S_ + s0];
        float v0 = fmaf(pw.x, Ev.x, loc.x);
        float v1 = fmaf(pw.y, Ev.y, loc.y);
        st2[r][s0]     = make_float2(v0, v0);
        st2[r][s0 + 1] = make_float2(v1, v1);
    }
    __syncthreads();

    unsigned long long acc2[16];
    #pragma unroll
    for (int r = 0; r < 16; r++) acc2[r] = 0ULL;

    const float2* wrow = &g_wcp[(size_t)p * S_];
    #pragma unroll 2
    for (int s4 = 0; s4 < 16; s4++) {
        const int k = s4 * 4;
        ulonglong2 wA = *(const ulonglong2*)&wrow[k];
        ulonglong2 wB = *(const ulonglong2*)&wrow[k + 2];
        #pragma unroll
        for (int r = 0; r < 16; r++) {
            const unsigned long long* sv = (const unsigned long long*)&st2[r][k];
            acc2[r] = fma2(sv[0], wA.x, acc2[r]);
            acc2[r] = fma2(sv[1], wA.y, acc2[r]);
            acc2[r] = fma2(sv[2], wB.x, acc2[r]);
            acc2[r] = fma2(sv[3], wB.y, acc2[r]);
        }
    }

    float acc0[16], acc1[16];
    const float d0 = Dv[c0] + 1.0f, d1 = Dv[c0 + 1] + 1.0f;
    #pragma unroll
    for (int r = 0; r < 16; r++) {
        float2 yv = *(float2*)&acc2[r];
        float2 xv = *(const float2*)&x[(size_t)(rowBase + r) * H_ + c0];
        float h0 = fmaf(d0, xv.x, yv.x);
        float h1 = fmaf(d1, xv.y, yv.y);
        acc0[r] = h0; acc1[r] = h1;
        float sm = h0 + h1;
        float sq = fmaf(h0, h0, h1 * h1);
        #pragma unroll
        for (int o = 16; o > 0; o >>= 1) {
            sm += __shfl_down_sync(0xffffffffu, sm, o);
            sq += __shfl_down_sync(0xffffffffu, sq, o);
        }
        if (lane == 0) { redS[w][r] = sm; redQ[w][r] = sq; }
    }
    __syncthreads();
    if (tid < 16) {
        float s = 0.0f, q = 0.0f;
        #pragma unroll
        for (int i = 0; i < 16; i++) { s += redS[i][tid]; q += redQ[i][tid]; }
        float mu = s * (1.0f / H_);
        float var = q * (1.0f / H_) - mu * mu;
        muA[tid] = mu;
        invA[tid] = rsqrtf(var + LN_EPSF);
    }
    __syncthreads();

    const float g0 = gamma[c0], g1 = gamma[c0 + 1];
    const float b0 = beta[c0],  b1 = beta[c0 + 1];
    #pragma unroll
    for (int r = 0; r < 16; r++) {
        const float mu = muA[r], inv = invA[r];
        float v0 = fmaf((acc0[r] - mu) * inv, g0, b0);
        float v1 = fmaf((acc1[r] - mu) * inv, g1, b1);
        const size_t off = (size_t)(rowBase + r) * H_ + c0;
        *(__half2*)&g_hn_hi[off] = __halves2half2(__float2half_rn(v0), __float2half_rn(v1));
    }
}

// ============================================================
// Kernel D: out = hn_hi @ wo_hi^T + bout, 1-seg fp16 MMA (K = 1024)
// ============================================================
__global__ void __launch_bounds__(256, 2) outGemmMMA(const float* __restrict__ bout,
                                                     float* __restrict__ out) {
    extern __shared__ char sm[];
    const uint32_t smb = smem_u32(sm);
    const int tid = threadIdx.x;
    const int lane = tid & 31, w = tid >> 5;
    const int wr = w >> 2, wc = w & 3;
    const int rowBase = blockIdx.x * 128;
    const int colBase = blockIdx.y * 128;

    auto loadStage = [&](int stage, int it) {
        const int k0  = it * KT;
        const uint32_t aB = smb + stage * 2 * STILE;
        const uint32_t bB = aB + STILE;
        #pragma unroll
        for (int t = 0; t < 4; t++) {
            const int c = tid + t * 256;
            const int r = c >> 3, j = c & 7;
            CP_ASYNC16(aB + r * SROW_B + j * 16, &g_hn_hi[(size_t)(rowBase + r) * H_ + k0 + j * 8]);
            CP_ASYNC16(bB + r * SROW_B + j * 16, &g_wo_hi[(size_t)(colBase + r) * H_ + k0 + j * 8]);
        }
        CP_COMMIT();
    };

    float acc[4][4][4];
    #pragma unroll
    for (int i = 0; i < 4; i++)
        #pragma unroll
        for (int j = 0; j < 4; j++)
            #pragma unroll
            for (int q = 0; q < 4; q++) acc[i][j][q] = 0.0f;

    loadStage(0, 0);
    const int NIT = 16;
    for (int it = 0; it < NIT; it++) {
        const int stage = it & 1;
        CP_WAIT0();
        __syncthreads();
        if (it + 1 < NIT) loadStage(stage ^ 1, it + 1);
        const uint32_t aT = smb + stage * 2 * STILE;
        const uint32_t bT = aT + STILE;
        #pragma unroll
        for (int ks = 0; ks < 4; ks++) {
            const int kb = ks * 32;
            uint32_t af[4][4];
            #pragma unroll
            for (int mi = 0; mi < 4; mi++) {
                const uint32_t addr = aT + (uint32_t)(wr * 64 + mi * 16 + (lane & 15)) * SROW_B
                                      + kb + ((lane >> 4) << 4);
                LDMX4(af[mi], addr);
            }
            uint32_t bf[2][4];
            #pragma unroll
            for (int nj = 0; nj < 2; nj++) {
                const uint32_t addr = bT + (uint32_t)(wc * 32 + nj * 16 + (lane & 15)) * SROW_B
                                      + kb + ((lane >> 4) << 4);
                LDMX4(bf[nj], addr);
            }
            #pragma unroll
            for (int mi = 0; mi < 4; mi++)
                #pragma unroll
                for (int ni = 0; ni < 4; ni++)
                    MMA_F16(acc[mi][ni], af[mi], bf[ni >> 1][ni & 1], bf[ni >> 1][(ni & 1) + 2]);
        }
        __syncthreads();
    }

    #pragma unroll
    for (int mi = 0; mi < 4; mi++) {
        const int r0 = rowBase + wr * 64 + mi * 16 + (lane >> 2);
        #pragma unroll
        for (int ni = 0; ni < 4; ni++) {
            const int c = colBase + wc * 32 + ni * 8 + (lane & 3) * 2;
            const float b0c = bout[c], b1c = bout[c + 1];
            float2 v0 = make_float2(acc[mi][ni][0] + b0c, acc[mi][ni][1] + b1c);
            float2 v1 = make_float2(acc[mi][ni][2] + b0c, acc[mi][ni][3] + b1c);
            *(float2*)&out[(size_t)r0 * H_ + c]       = v0;
            *(float2*)&out[(size_t)(r0 + 8) * H_ + c] = v1;
        }
    }
}

// ============================================================
// launch
// ============================================================
extern "C" void kernel_launch(void* const* d_in, const int* in_sizes, int n_in,
                              void* d_out, int out_size) {
    const float* x     = (const float*)d_in[0];
    const float* A_log = (const float*)d_in[1];
    const float* WB    = (const float*)d_in[2];
    const float* WC    = (const float*)d_in[3];
    const float* Dv    = (const float*)d_in[4];
    const float* Wg    = (const float*)d_in[5];
    const float* bg    = (const float*)d_in[6];
    const float* Wout  = (const float*)d_in[7];
    const float* bout  = (const float*)d_in[8];
    const float* gamma = (const float*)d_in[9];
    const float* beta  = (const float*)d_in[10];

    float* out = (float*)d_out;
    float* finalState = (out_size >= M_ * H_ + B_ * S_) ? out + (size_t)M_ * H_ : nullptr;

    cudaFuncSetAttribute(outGemmMMA, cudaFuncAttributeMaxDynamicSharedMemorySize, SMEM_D);
    cudaFuncSetAttribute(uGemmMMA,   cudaFuncAttributeMaxDynamicSharedMemorySize, SMEM_U);

    wSplit<<<H_*H_/1024, 256>>>(Wout);
    wgbHalf<<<128, 256>>>(Wg, WB);
    wcPack<<<H_/2, 64>>>(WC);
    aPowK<<<1, 64>>>(A_log);
    xSplitH<<<M_*H_/1024, 256>>>(x);
    uGemmMMA<<<M_/64, 256, SMEM_U>>>(bg);
    scanLS<<<B_, 1024>>>(A_log, finalState);
    yLNT<<<M_/16, 512>>>(x, Dv, gamma, beta);
    dim3 gD(M_/128, H_/128);
    outGemmMMA<<<gD, 256, SMEM_D>>>(bout, out);
}

// round 14
// speedup vs baseline: 1.2077x; 1.1559x over previous
#include <cuda_runtime.h>
#include <cuda_bf16.h>
#include <cuda_fp16.h>
#include <math.h>
#include <stdint.h>

#define B_   4
#define T_   4096
#define H_   1024
#define S_   64
#define M_   (B_*T_)     // 16384 rows
#define NCH  64
#define TC   64
#define LN_EPSF 1e-5f

// ---- scratch ----
__device__ float g_L[B_*NCH*S_];                   // chunk carries
__device__ float g_E[B_*NCH*S_];                   // entering state per chunk
__device__ float g_aPow[TC*S_];                    // a_s^(i+1)
__device__ float g_states[M_*S_];                  // LOCAL states (corrected in yLNT)
__device__ __half g_hn_hi[(size_t)M_*H_];          // 32 MB
__device__ __half g_wo_hi[(size_t)H_*H_];          // 2 MB
__device__ __half g_wgb_h[128*H_];                 // fp16 [2s]=Wg[s], [2s+1]=WB[s]
__device__ float2 g_wcp[(H_/2)*S_];                // WC packed col-pairwise

// ============================================================
// PTX helpers
// ============================================================
__device__ __forceinline__ uint32_t smem_u32(const void* p) {
    uint32_t a;
    asm("{ .reg .u64 t; cvta.to.shared.u64 t, %1; cvt.u32.u64 %0, t; }" : "=r"(a) : "l"(p));
    return a;
}
#define CP_ASYNC16(dst, src) \
    asm volatile("cp.async.cg.shared.global [%0], [%1], 16;" :: "r"(dst), "l"(src) : "memory")
#define CP_COMMIT() asm volatile("cp.async.commit_group;" ::: "memory")
#define CP_WAIT0()  asm volatile("cp.async.wait_group 0;" ::: "memory")

#define LDMX4(r, addr) \
    asm volatile("ldmatrix.sync.aligned.m8n8.x4.shared.b16 {%0,%1,%2,%3}, [%4];" \
        : "=r"((r)[0]), "=r"((r)[1]), "=r"((r)[2]), "=r"((r)[3]) : "r"(addr))

#define MMA_F16(c, a, b0v, b1v) \
    asm volatile("mma.sync.aligned.m16n8k16.row.col.f32.f16.f16.f32 " \
        "{%0,%1,%2,%3},{%4,%5,%6,%7},{%8,%9},{%0,%1,%2,%3};" \
        : "+f"((c)[0]), "+f"((c)[1]), "+f"((c)[2]), "+f"((c)[3]) \
        : "r"((a)[0]), "r"((a)[1]), "r"((a)[2]), "r"((a)[3]), "r"(b0v), "r"(b1v))

__device__ __forceinline__ unsigned long long fma2(unsigned long long a,
                                                   unsigned long long b,
                                                   unsigned long long c) {
    unsigned long long d;
    asm("fma.rn.f32x2 %0, %1, %2, %3;" : "=l"(d) : "l"(a), "l"(b), "l"(c));
    return d;
}

// ============================================================
// prepAll: range-specialized prep (Wout fp16, Wg/WB interleave fp16,
// WC col-pair pack, aPow table). Grid 1281 x 256.
// ============================================================
__global__ void __launch_bounds__(256) prepAll(const float* __restrict__ Wout,
                                               const float* __restrict__ Wg,
                                               const float* __restrict__ WB,
                                               const float* __restrict__ WC,
                                               const float* __restrict__ A_log) {
    const int bid = blockIdx.x;
    const int tid = threadIdx.x;
    if (bid < 1024) {                              // Wout -> fp16
        const int base = (bid * 256 + tid) * 4;
        #pragma unroll
        for (int t = 0; t < 4; t++)
            g_wo_hi[base + t] = __float2half_rn(Wout[base + t]);
    } else if (bid < 1152) {                       // Wg/WB interleave
        const int r = bid - 1024;
        const int s = r >> 1;
        const float* src = (r & 1) ? &WB[(size_t)s * H_] : &Wg[(size_t)s * H_];
        for (int k = tid * 4; k < H_; k += 1024) {
            #pragma unroll
            for (int t = 0; t < 4; t++)
                g_wgb_h[(size_t)r * H_ + k + t] = __float2half_rn(src[k + t]);
        }
    } else if (bid < 1280) {                       // WC pack: 4 pairs per block
        const int p = (bid - 1152) * 4 + (tid >> 6);
        const int k = tid & 63;
        g_wcp[p * S_ + k] = make_float2(WC[(size_t)(2 * p) * S_ + k],
                                        WC[(size_t)(2 * p + 1) * S_ + k]);
    } else {                                       // aPow
        if (tid < S_) {
            const float a = expf(A_log[tid]);
            float pw = 1.0f;
            for (int i = 0; i < TC; i++) {
                pw *= a;
                g_aPow[i * S_ + tid] = pw;
            }
        }
    }
}

// ============================================================
// GEMM geometry
// ============================================================
#define KT     64
#define SROW_B 144           // bytes per smem row (72 x b16)
#define STILE  (128*SROW_B)  // 18432 (128-row tile)
#define SMEM_D (4*STILE)     // 73728

// ============================================================
// Kernel A: fused uGemm + local scan.
// CTA = 64 rows = chunk c of batch b. fp16 1-seg MMA, K=1024.
// A tile converted in-kernel from fp32 x (reg-prefetched LDG).
// Epilogue: u -> smem -> local scan -> local states + chunk carry.
// ============================================================
#define UA_TILE (64*SROW_B)              // 9216  (single buffer)
#define UB_OFF  UA_TILE
#define U_SMEM  (UA_TILE + 2*128*SROW_B) // 9216 + 36864 = 46080
#define SU_STRIDE 68                     // floats, padded

__global__ void __launch_bounds__(256, 2) uGemmMMA(const float* __restrict__ x,
                                                   const float* __restrict__ A_log,
                                                   const float* __restrict__ bg) {
    extern __shared__ char sm[];
    const uint32_t smb = smem_u32(sm);
    float* su = (float*)sm;                       // reused after MMA: [64][68]
    const int tid = threadIdx.x;
    const int lane = tid & 31, w = tid >> 5;
    const int wr = w >> 2, wc = w & 3;            // 2 x 4 warps; warp tile 32x32
    const int rowBase = blockIdx.x * 64;

    // A fp32 prefetch mapping: thread -> (row = tid>>2, 16 cols from (tid&3)*16)
    const int ar = tid >> 2;
    const int ac = (tid & 3) * 16;
    const float* xrow = &x[(size_t)(rowBase + ar) * H_ + ac];

    auto loadB = [&](int stage, int it) {
        const int k0 = it * KT;
        const uint32_t bB = smb + UB_OFF + stage * (128 * SROW_B);
        #pragma unroll
        for (int t = 0; t < 4; t++) {
            const int c = tid + t * 256;
            const int r = c >> 3, j = c & 7;
            CP_ASYNC16(bB + r * SROW_B + j * 16, &g_wgb_h[(size_t)r * H_ + k0 + j * 8]);
        }
        CP_COMMIT();
    };

    float4 aReg[4];
    #pragma unroll
    for (int q = 0; q < 4; q++) aReg[q] = *(const float4*)&xrow[0 * KT + q * 4];

    float acc[2][4][4];
    #pragma unroll
    for (int i = 0; i < 2; i++)
        #pragma unroll
        for (int j = 0; j < 4; j++)
            #pragma unroll
            for (int q = 0; q < 4; q++) acc[i][j][q] = 0.0f;

    loadB(0, 0);
    const int NIT = 16;
    for (int it = 0; it < NIT; it++) {
        const int stage = it & 1;
        CP_WAIT0();
        __syncthreads();                          // B ready; prev MMA done (A tile safe)
        {   // convert A regs -> fp16 A tile
            const uint32_t aAddr = smb + (uint32_t)ar * SROW_B + ac * 2;
            #pragma unroll
            for (int q = 0; q < 4; q++) {
                __half2 h0 = __halves2half2(__float2half_rn(aReg[q].x), __float2half_rn(aReg[q].y));
                __half2 h1 = __halves2half2(__float2half_rn(aReg[q].z), __float2half_rn(aReg[q].w));
                uint32_t u0 = *(uint32_t*)&h0, u1 = *(uint32_t*)&h1;
                asm volatile("st.shared.v2.u32 [%0], {%1, %2};"
                             :: "r"(aAddr + q * 8), "r"(u0), "r"(u1) : "memory");
            }
        }
        if (it + 1 < NIT) {
            loadB(stage ^ 1, it + 1);
            #pragma unroll
            for (int q = 0; q < 4; q++)
                aReg[q] = *(const float4*)&xrow[(it + 1) * KT + q * 4];
        }
        __syncthreads();                          // A tile visible to all warps

        const uint32_t aT = smb;
        const uint32_t bT = smb + UB_OFF + stage * (128 * SROW_B);
        #pragma unroll
        for (int ks = 0; ks < 4; ks++) {
            const int kb = ks * 32;
            uint32_t af[2][4];
            #pragma unroll
            for (int mi = 0; mi < 2; mi++) {
                const uint32_t addr = aT + (uint32_t)(wr * 32 + mi * 16 + (lane & 15)) * SROW_B
                                      + kb + ((lane >> 4) << 4);
                LDMX4(af[mi], addr);
            }
            uint32_t bf[2][4];
            #pragma unroll
            for (int nj = 0; nj < 2; nj++) {
                const uint32_t addr = bT + (uint32_t)(wc * 32 + nj * 16 + (lane & 15)) * SROW_B
                                      + kb + ((lane >> 4) << 4);
                LDMX4(bf[nj], addr);
            }
            #pragma unroll
            for (int mi = 0; mi < 2; mi++)
                #pragma unroll
                for (int ni = 0; ni < 4; ni++)
                    MMA_F16(acc[mi][ni], af[mi], bf[ni >> 1][ni & 1], bf[ni >> 1][(ni & 1) + 2]);
        }
        __syncthreads();
    }

    // ---- epilogue: u -> smem ----
    #pragma unroll
    for (int mi = 0; mi < 2; mi++) {
        const int lr = wr * 32 + mi * 16 + (lane >> 2);   // local row 0..63
        #pragma unroll
        for (int ni = 0; ni < 4; ni++) {
            const int c = wc * 32 + ni * 8 + (lane & 3) * 2;
            const int s = c >> 1;
            const float bgs = bg[s];
            float gate0 = 1.0f / (1.0f + expf(-(acc[mi][ni][0] + bgs)));
            float gate1 = 1.0f / (1.0f + expf(-(acc[mi][ni][2] + bgs)));
            su[lr * SU_STRIDE + s]       = gate0 * acc[mi][ni][1];
            su[(lr + 8) * SU_STRIDE + s] = gate1 * acc[mi][ni][3];
        }
    }
    __syncthreads();

    // ---- local scan in smem (64 threads, one per s) ----
    if (tid < S_) {
        const int s = tid;
        const float a = expf(A_log[s]);
        float st = 0.0f;
        #pragma unroll 8
        for (int i = 0; i < TC; i++) {
            st = fmaf(a, st, su[i * SU_STRIDE + s]);
            su[i * SU_STRIDE + s] = st;           // local state
        }
        const int b = rowBase >> 12;              // /4096
        const int c = (rowBase >> 6) & 63;
        g_L[((size_t)b * NCH + c) * S_ + s] = st;
    }
    __syncthreads();

    // ---- coalesced local-state writeback ----
    {
        const int row = tid >> 2, s0 = (tid & 3) * 16;
        #pragma unroll
        for (int q = 0; q < 4; q++) {
            float4 v = *(const float4*)&su[row * SU_STRIDE + s0 + q * 4];
            *(float4*)&g_states[(size_t)(rowBase + row) * S_ + s0 + q * 4] = v;
        }
    }
}

// ============================================================
// scanCarry: serial cross-chunk carry (reg-batched loads)
// ============================================================
__global__ void scanCarry(const float* __restrict__ A_log, float* __restrict__ finalState) {
    const int tid = threadIdx.x;
    const int b = tid / S_, s = tid % S_;
    const float a = expf(A_log[s]);
    float aTC = 1.0f;
    #pragma unroll
    for (int i = 0; i < TC; i++) aTC *= a;
    float L[NCH];
    #pragma unroll
    for (int c = 0; c < NCH; c++)
        L[c] = g_L[((size_t)b * NCH + c) * S_ + s];
    float E = 0.0f;
    #pragma unroll
    for (int c = 0; c < NCH; c++) {
        g_E[((size_t)b * NCH + c) * S_ + s] = E;
        E = fmaf(aTC, E, L[c]);
    }
    if (finalState) finalState[b * S_ + s] = E;
}

// ============================================================
// Kernel C: tiled yLN with packed f32x2 inner product + fused scan
// correction: states[i] = local[i] + aPow[i]*E.
// ============================================================
__global__ void __launch_bounds__(512) yLNT(const float* __restrict__ x,
                                            const float* __restrict__ Dv,
                                            const float* __restrict__ gamma,
                                            const float* __restrict__ beta) {
    __shared__ float2 st2[16][64];
    __shared__ float redS[16][16], redQ[16][16];
    __shared__ float muA[16], invA[16];
    const int tid = threadIdx.x;
    const int lane = tid & 31, w = tid >> 5;
    const int rowBase = blockIdx.x * 16;
    const int p = tid;
    const int c0 = p * 2;

    {   // load local states, apply correction, duplicate
        const int r = tid >> 5, s0 = (tid & 31) * 2;
        const int eRow = rowBase >> 6;
        const int i0 = rowBase & 63;
        float2 loc = *(const float2*)&g_states[(size_t)(rowBase + r) * S_ + s0];
        float2 Ev  = *(const float2*)&g_E[(size_t)eRow * S_ + s0];
        float2 pw  = *(const float2*)&g_aPow[(i0 + r) * S_ + s0];
        float v0 = fmaf(pw.x, Ev.x, loc.x);
        float v1 = fmaf(pw.y, Ev.y, loc.y);
        st2[r][s0]     = make_float2(v0, v0);
        st2[r][s0 + 1] = make_float2(v1, v1);
    }
    __syncthreads();

    unsigned long long acc2[16];
    #pragma unroll
    for (int r = 0; r < 16; r++) acc2[r] = 0ULL;

    const float2* wrow = &g_wcp[(size_t)p * S_];
    #pragma unroll 2
    for (int s4 = 0; s4 < 16; s4++) {
        const int k = s4 * 4;
        ulonglong2 wA = *(const ulonglong2*)&wrow[k];
        ulonglong2 wB = *(const ulonglong2*)&wrow[k + 2];
        #pragma unroll
        for (int r = 0; r < 16; r++) {
            const unsigned long long* sv = (const unsigned long long*)&st2[r][k];
            acc2[r] = fma2(sv[0], wA.x, acc2[r]);
            acc2[r] = fma2(sv[1], wA.y, acc2[r]);
            acc2[r] = fma2(sv[2], wB.x, acc2[r]);
            acc2[r] = fma2(sv[3], wB.y, acc2[r]);
        }
    }

    float acc0[16], acc1[16];
    const float d0 = Dv[c0] + 1.0f, d1 = Dv[c0 + 1] + 1.0f;
    #pragma unroll
    for (int r = 0; r < 16; r++) {
        float2 yv = *(float2*)&acc2[r];
        float2 xv = *(const float2*)&x[(size_t)(rowBase + r) * H_ + c0];
        float h0 = fmaf(d0, xv.x, yv.x);
        float h1 = fmaf(d1, xv.y, yv.y);
        acc0[r] = h0; acc1[r] = h1;
        float sm = h0 + h1;
        float sq = fmaf(h0, h0, h1 * h1);
        #pragma unroll
        for (int o = 16; o > 0; o >>= 1) {
            sm += __shfl_down_sync(0xffffffffu, sm, o);
            sq += __shfl_down_sync(0xffffffffu, sq, o);
        }
        if (lane == 0) { redS[w][r] = sm; redQ[w][r] = sq; }
    }
    __syncthreads();
    if (tid < 16) {
        float s = 0.0f, q = 0.0f;
        #pragma unroll
        for (int i = 0; i < 16; i++) { s += redS[i][tid]; q += redQ[i][tid]; }
        float mu = s * (1.0f / H_);
        float var = q * (1.0f / H_) - mu * mu;
        muA[tid] = mu;
        invA[tid] = rsqrtf(var + LN_EPSF);
    }
    __syncthreads();

    const float g0 = gamma[c0], g1 = gamma[c0 + 1];
    const float b0 = beta[c0],  b1 = beta[c0 + 1];
    #pragma unroll
    for (int r = 0; r < 16; r++) {
        const float mu = muA[r], inv = invA[r];
        float v0 = fmaf((acc0[r] - mu) * inv, g0, b0);
        float v1 = fmaf((acc1[r] - mu) * inv, g1, b1);
        const size_t off = (size_t)(rowBase + r) * H_ + c0;
        *(__half2*)&g_hn_hi[off] = __halves2half2(__float2half_rn(v0), __float2half_rn(v1));
    }
}

// ============================================================
// Kernel D: out = hn_hi @ wo_hi^T + bout, 1-seg fp16 MMA (K = 1024)
// ============================================================
__global__ void __launch_bounds__(256, 2) outGemmMMA(const float* __restrict__ bout,
                                                     float* __restrict__ out) {
    extern __shared__ char sm[];
    const uint32_t smb = smem_u32(sm);
    const int tid = threadIdx.x;
    const int lane = tid & 31, w = tid >> 5;
    const int wr = w >> 2, wc = w & 3;
    const int rowBase = blockIdx.x * 128;
    const int colBase = blockIdx.y * 128;

    auto loadStage = [&](int stage, int it) {
        const int k0  = it * KT;
        const uint32_t aB = smb + stage * 2 * STILE;
        const uint32_t bB = aB + STILE;
        #pragma unroll
        for (int t = 0; t < 4; t++) {
            const int c = tid + t * 256;
            const int r = c >> 3, j = c & 7;
            CP_ASYNC16(aB + r * SROW_B + j * 16, &g_hn_hi[(size_t)(rowBase + r) * H_ + k0 + j * 8]);
            CP_ASYNC16(bB + r * SROW_B + j * 16, &g_wo_hi[(size_t)(colBase + r) * H_ + k0 + j * 8]);
        }
        CP_COMMIT();
    };

    float acc[4][4][4];
    #pragma unroll
    for (int i = 0; i < 4; i++)
        #pragma unroll
        for (int j = 0; j < 4; j++)
            #pragma unroll
            for (int q = 0; q < 4; q++) acc[i][j][q] = 0.0f;

    loadStage(0, 0);
    const int NIT = 16;
    for (int it = 0; it < NIT; it++) {
        const int stage = it & 1;
        CP_WAIT0();
        __syncthreads();
        if (it + 1 < NIT) loadStage(stage ^ 1, it + 1);
        const uint32_t aT = smb + stage * 2 * STILE;
        const uint32_t bT = aT + STILE;
        #pragma unroll
        for (int ks = 0; ks < 4; ks++) {
            const int kb = ks * 32;
            uint32_t af[4][4];
            #pragma unroll
            for (int mi = 0; mi < 4; mi++) {
                const uint32_t addr = aT + (uint32_t)(wr * 64 + mi * 16 + (lane & 15)) * SROW_B
                                      + kb + ((lane >> 4) << 4);
                LDMX4(af[mi], addr);
            }
            uint32_t bf[2][4];
            #pragma unroll
            for (int nj = 0; nj < 2; nj++) {
                const uint32_t addr = bT + (uint32_t)(wc * 32 + nj * 16 + (lane & 15)) * SROW_B
                                      + kb + ((lane >> 4) << 4);
                LDMX4(bf[nj], addr);
            }
            #pragma unroll
            for (int mi = 0; mi < 4; mi++)
                #pragma unroll
                for (int ni = 0; ni < 4; ni++)
                    MMA_F16(acc[mi][ni], af[mi], bf[ni >> 1][ni & 1], bf[ni >> 1][(ni & 1) + 2]);
        }
        __syncthreads();
    }

    #pragma unroll
    for (int mi = 0; mi < 4; mi++) {
        const int r0 = rowBase + wr * 64 + mi * 16 + (lane >> 2);
        #pragma unroll
        for (int ni = 0; ni < 4; ni++) {
            const int c = colBase + wc * 32 + ni * 8 + (lane & 3) * 2;
            const float b0c = bout[c], b1c = bout[c + 1];
            float2 v0 = make_float2(acc[mi][ni][0] + b0c, acc[mi][ni][1] + b1c);
            float2 v1 = make_float2(acc[mi][ni][2] + b0c, acc[mi][ni][3] + b1c);
            *(float2*)&out[(size_t)r0 * H_ + c]       = v0;
            *(float2*)&out[(size_t)(r0 + 8) * H_ + c] = v1;
        }
    }
}

// ============================================================
// launch
// ============================================================
extern "C" void kernel_launch(void* const* d_in, const int* in_sizes, int n_in,
                              void* d_out, int out_size) {
    const float* x     = (const float*)d_in[0];
    const float* A_log = (const float*)d_in[1];
    const float* WB    = (const float*)d_in[2];
    const float* WC    = (const float*)d_in[3];
    const float* Dv    = (const float*)d_in[4];
    const float* Wg    = (const float*)d_in[5];
    const float* bg    = (const float*)d_in[6];
    const float* Wout  = (const float*)d_in[7];
    const float* bout  = (const float*)d_in[8];
    const float* gamma = (const float*)d_in[9];
    const float* beta  = (const float*)d_in[10];

    float* out = (float*)d_out;
    float* finalState = (out_size >= M_ * H_ + B_ * S_) ? out + (size_t)M_ * H_ : nullptr;

    cudaFuncSetAttribute(outGemmMMA, cudaFuncAttributeMaxDynamicSharedMemorySize, SMEM_D);
    cudaFuncSetAttribute(uGemmMMA,   cudaFuncAttributeMaxDynamicSharedMemorySize, U_SMEM);

    prepAll<<<1281, 256>>>(Wout, Wg, WB, WC, A_log);
    uGemmMMA<<<M_/64, 256, U_SMEM>>>(x, A_log, bg);
    scanCarry<<<1, B_*S_>>>(A_log, finalState);
    yLNT<<<M_/16, 512>>>(x, Dv, gamma, beta);
    dim3 gD(M_/128, H_/128);
    outGemmMMA<<<gD, 256, SMEM_D>>>(bout, out);
}

// round 15
// speedup vs baseline: 1.6905x; 1.3998x over previous
#include <cuda_runtime.h>
#include <cuda_bf16.h>
#include <cuda_fp16.h>
#include <math.h>
#include <stdint.h>

#define B_   4
#define T_   4096
#define H_   1024
#define S_   64
#define M_   (B_*T_)     // 16384 rows
#define NCH  64
#define TC   64
#define LN_EPSF 1e-5f

// ---- scratch ----
__device__ float g_L[B_*NCH*S_];
__device__ float g_E[B_*NCH*S_];
__device__ float g_aPow[TC*S_];
__device__ float g_states[M_*S_];                  // LOCAL states
__device__ __half g_h[(size_t)M_*H_];              // 32 MB pre-LN hidden
__device__ __half g_hn_hi[(size_t)M_*H_];          // 32 MB
__device__ __half g_wo_hi[(size_t)H_*H_];          // 2 MB
__device__ __half g_wgb_h[128*H_];
__device__ __half g_wc_h[H_*S_];                   // WC fp16, 128 KB

// ============================================================
// PTX helpers
// ============================================================
__device__ __forceinline__ uint32_t smem_u32(const void* p) {
    uint32_t a;
    asm("{ .reg .u64 t; cvta.to.shared.u64 t, %1; cvt.u32.u64 %0, t; }" : "=r"(a) : "l"(p));
    return a;
}
#define CP_ASYNC16(dst, src) \
    asm volatile("cp.async.cg.shared.global [%0], [%1], 16;" :: "r"(dst), "l"(src) : "memory")
#define CP_COMMIT() asm volatile("cp.async.commit_group;" ::: "memory")
#define CP_WAIT0()  asm volatile("cp.async.wait_group 0;" ::: "memory")

#define LDMX4(r, addr) \
    asm volatile("ldmatrix.sync.aligned.m8n8.x4.shared.b16 {%0,%1,%2,%3}, [%4];" \
        : "=r"((r)[0]), "=r"((r)[1]), "=r"((r)[2]), "=r"((r)[3]) : "r"(addr))

#define MMA_F16(c, a, b0v, b1v) \
    asm volatile("mma.sync.aligned.m16n8k16.row.col.f32.f16.f16.f32 " \
        "{%0,%1,%2,%3},{%4,%5,%6,%7},{%8,%9},{%0,%1,%2,%3};" \
        : "+f"((c)[0]), "+f"((c)[1]), "+f"((c)[2]), "+f"((c)[3]) \
        : "r"((a)[0]), "r"((a)[1]), "r"((a)[2]), "r"((a)[3]), "r"(b0v), "r"(b1v))

// ============================================================
// prepAll: Wout fp16, Wg/WB interleave fp16, WC fp16, aPow.
// Grid 1217 x 256.
// ============================================================
__global__ void __launch_bounds__(256) prepAll(const float* __restrict__ Wout,
                                               const float* __restrict__ Wg,
                                               const float* __restrict__ WB,
                                               const float* __restrict__ WC,
                                               const float* __restrict__ A_log) {
    const int bid = blockIdx.x;
    const int tid = threadIdx.x;
    if (bid < 1024) {                              // Wout -> fp16
        const int base = (bid * 256 + tid) * 4;
        #pragma unroll
        for (int t = 0; t < 4; t++)
            g_wo_hi[base + t] = __float2half_rn(Wout[base + t]);
    } else if (bid < 1152) {                       // Wg/WB interleave
        const int r = bid - 1024;
        const int s = r >> 1;
        const float* src = (r & 1) ? &WB[(size_t)s * H_] : &Wg[(size_t)s * H_];
        for (int k = tid * 4; k < H_; k += 1024) {
            #pragma unroll
            for (int t = 0; t < 4; t++)
                g_wgb_h[(size_t)r * H_ + k + t] = __float2half_rn(src[k + t]);
        }
    } else if (bid < 1216) {                       // WC -> fp16 (65536 vals)
        const int base = ((bid - 1152) * 256 + tid) * 4;
        #pragma unroll
        for (int t = 0; t < 4; t++)
            g_wc_h[base + t] = __float2half_rn(WC[base + t]);
    } else {                                       // aPow
        if (tid < S_) {
            const float a = expf(A_log[tid]);
            float pw = 1.0f;
            for (int i = 0; i < TC; i++) {
                pw *= a;
                g_aPow[i * S_ + tid] = pw;
            }
        }
    }
}

// ============================================================
// GEMM geometry
// ============================================================
#define KT     64
#define SROW_B 144           // bytes per smem row (72 x b16)
#define STILE  (128*SROW_B)  // 18432
#define SMEM_D (4*STILE)     // 73728
#define Y_SMEM (2*STILE)     // 36864

// ============================================================
// Kernel A: fused uGemm + local scan (R10-proven).
// ============================================================
#define UA_TILE (64*SROW_B)
#define UB_OFF  UA_TILE
#define U_SMEM  (UA_TILE + 2*128*SROW_B)
#define SU_STRIDE 68

__global__ void __launch_bounds__(256, 2) uGemmMMA(const float* __restrict__ x,
                                                   const float* __restrict__ A_log,
                                                   const float* __restrict__ bg) {
    extern __shared__ char sm[];
    const uint32_t smb = smem_u32(sm);
    float* su = (float*)sm;
    const int tid = threadIdx.x;
    const int lane = tid & 31, w = tid >> 5;
    const int wr = w >> 2, wc = w & 3;
    const int rowBase = blockIdx.x * 64;

    const int ar = tid >> 2;
    const int ac = (tid & 3) * 16;
    const float* xrow = &x[(size_t)(rowBase + ar) * H_ + ac];

    auto loadB = [&](int stage, int it) {
        const int k0 = it * KT;
        const uint32_t bB = smb + UB_OFF + stage * (128 * SROW_B);
        #pragma unroll
        for (int t = 0; t < 4; t++) {
            const int c = tid + t * 256;
            const int r = c >> 3, j = c & 7;
            CP_ASYNC16(bB + r * SROW_B + j * 16, &g_wgb_h[(size_t)r * H_ + k0 + j * 8]);
        }
        CP_COMMIT();
    };

    float4 aReg[4];
    #pragma unroll
    for (int q = 0; q < 4; q++) aReg[q] = *(const float4*)&xrow[0 * KT + q * 4];

    float acc[2][4][4];
    #pragma unroll
    for (int i = 0; i < 2; i++)
        #pragma unroll
        for (int j = 0; j < 4; j++)
            #pragma unroll
            for (int q = 0; q < 4; q++) acc[i][j][q] = 0.0f;

    loadB(0, 0);
    const int NIT = 16;
    for (int it = 0; it < NIT; it++) {
        const int stage = it & 1;
        CP_WAIT0();
        __syncthreads();
        {
            const uint32_t aAddr = smb + (uint32_t)ar * SROW_B + ac * 2;
            #pragma unroll
            for (int q = 0; q < 4; q++) {
                __half2 h0 = __halves2half2(__float2half_rn(aReg[q].x), __float2half_rn(aReg[q].y));
                __half2 h1 = __halves2half2(__float2half_rn(aReg[q].z), __float2half_rn(aReg[q].w));
                uint32_t u0 = *(uint32_t*)&h0, u1 = *(uint32_t*)&h1;
                asm volatile("st.shared.v2.u32 [%0], {%1, %2};"
                             :: "r"(aAddr + q * 8), "r"(u0), "r"(u1) : "memory");
            }
        }
        if (it + 1 < NIT) {
            loadB(stage ^ 1, it + 1);
            #pragma unroll
            for (int q = 0; q < 4; q++)
                aReg[q] = *(const float4*)&xrow[(it + 1) * KT + q * 4];
        }
        __syncthreads();

        const uint32_t aT = smb;
        const uint32_t bT = smb + UB_OFF + stage * (128 * SROW_B);
        #pragma unroll
        for (int ks = 0; ks < 4; ks++) {
            const int kb = ks * 32;
            uint32_t af[2][4];
            #pragma unroll
            for (int mi = 0; mi < 2; mi++) {
                const uint32_t addr = aT + (uint32_t)(wr * 32 + mi * 16 + (lane & 15)) * SROW_B
                                      + kb + ((lane >> 4) << 4);
                LDMX4(af[mi], addr);
            }
            uint32_t bf[2][4];
            #pragma unroll
            for (int nj = 0; nj < 2; nj++) {
                const uint32_t addr = bT + (uint32_t)(wc * 32 + nj * 16 + (lane & 15)) * SROW_B
                                      + kb + ((lane >> 4) << 4);
                LDMX4(bf[nj], addr);
            }
            #pragma unroll
            for (int mi = 0; mi < 2; mi++)
                #pragma unroll
                for (int ni = 0; ni < 4; ni++)
                    MMA_F16(acc[mi][ni], af[mi], bf[ni >> 1][ni & 1], bf[ni >> 1][(ni & 1) + 2]);
        }
        __syncthreads();
    }

    #pragma unroll
    for (int mi = 0; mi < 2; mi++) {
        const int lr = wr * 32 + mi * 16 + (lane >> 2);
        #pragma unroll
        for (int ni = 0; ni < 4; ni++) {
            const int c = wc * 32 + ni * 8 + (lane & 3) * 2;
            const int s = c >> 1;
            const float bgs = bg[s];
            float gate0 = 1.0f / (1.0f + expf(-(acc[mi][ni][0] + bgs)));
            float gate1 = 1.0f / (1.0f + expf(-(acc[mi][ni][2] + bgs)));
            su[lr * SU_STRIDE + s]       = gate0 * acc[mi][ni][1];
            su[(lr + 8) * SU_STRIDE + s] = gate1 * acc[mi][ni][3];
        }
    }
    __syncthreads();

    if (tid < S_) {
        const int s = tid;
        const float a = expf(A_log[s]);
        float st = 0.0f;
        #pragma unroll 8
        for (int i = 0; i < TC; i++) {
            st = fmaf(a, st, su[i * SU_STRIDE + s]);
            su[i * SU_STRIDE + s] = st;
        }
        const int b = rowBase >> 12;
        const int c = (rowBase >> 6) & 63;
        g_L[((size_t)b * NCH + c) * S_ + s] = st;
    }
    __syncthreads();

    {
        const int row = tid >> 2, s0 = (tid & 3) * 16;
        #pragma unroll
        for (int q = 0; q < 4; q++) {
            float4 v = *(const float4*)&su[row * SU_STRIDE + s0 + q * 4];
            *(float4*)&g_states[(size_t)(rowBase + row) * S_ + s0 + q * 4] = v;
        }
    }
}

// ============================================================
// scanCarry
// ============================================================
__global__ void scanCarry(const float* __restrict__ A_log, float* __restrict__ finalState) {
    const int tid = threadIdx.x;
    const int b = tid / S_, s = tid % S_;
    const float a = expf(A_log[s]);
    float aTC = 1.0f;
    #pragma unroll
    for (int i = 0; i < TC; i++) aTC *= a;
    float L[NCH];
    #pragma unroll
    for (int c = 0; c < NCH; c++)
        L[c] = g_L[((size_t)b * NCH + c) * S_ + s];
    float E = 0.0f;
    #pragma unroll
    for (int c = 0; c < NCH; c++) {
        g_E[((size_t)b * NCH + c) * S_ + s] = E;
        E = fmaf(aTC, E, L[c]);
    }
    if (finalState) finalState[b * S_ + s] = E;
}

// ============================================================
// yGemmMMA: h = (corrected states) @ WC^T + (D+1)*x, fp16 MMA, K=64.
// CTA 128x128, single K stage. A-load fuses correction + fp16 convert.
// ============================================================
__global__ void __launch_bounds__(256, 2) yGemmMMA(const float* __restrict__ x,
                                                   const float* __restrict__ Dv) {
    extern __shared__ char sm[];
    const uint32_t smb = smem_u32(sm);
    const int tid = threadIdx.x;
    const int lane = tid & 31, w = tid >> 5;
    const int wr = w >> 2, wc = w & 3;
    const int rowBase = blockIdx.x * 128;
    const int colBase = blockIdx.y * 128;

    // B: WC fp16 [colBase..+128][64] via cp.async (128 rows x 128 B)
    {
        const uint32_t bB = smb + STILE;
        #pragma unroll
        for (int t = 0; t < 4; t++) {
            const int c = tid + t * 256;
            const int r = c >> 3, j = c & 7;
            CP_ASYNC16(bB + r * SROW_B + j * 16, &g_wc_h[(size_t)(colBase + r) * S_ + j * 8]);
        }
        CP_COMMIT();
    }

    // A: corrected states -> fp16 (2 threads/row, 32 s-vals each)
    {
        const int r = tid >> 1;
        const int s0 = (tid & 1) * 32;
        const int grow = rowBase + r;
        const int eRow = grow >> 6;
        const int i = grow & 63;
        const uint32_t aAddr = smb + (uint32_t)r * SROW_B + s0 * 2;
        #pragma unroll
        for (int q = 0; q < 8; q++) {
            float4 loc = *(const float4*)&g_states[(size_t)grow * S_ + s0 + q * 4];
            float4 Ev  = *(const float4*)&g_E[(size_t)eRow * S_ + s0 + q * 4];
            float4 pw  = *(const float4*)&g_aPow[i * S_ + s0 + q * 4];
            float v0 = fmaf(pw.x, Ev.x, loc.x);
            float v1 = fmaf(pw.y, Ev.y, loc.y);
            float v2 = fmaf(pw.z, Ev.z, loc.z);
            float v3 = fmaf(pw.w, Ev.w, loc.w);
            __half2 h0 = __halves2half2(__float2half_rn(v0), __float2half_rn(v1));
            __half2 h1 = __halves2half2(__float2half_rn(v2), __float2half_rn(v3));
            uint32_t u0 = *(uint32_t*)&h0, u1 = *(uint32_t*)&h1;
            asm volatile("st.shared.v2.u32 [%0], {%1, %2};"
                         :: "r"(aAddr + q * 8), "r"(u0), "r"(u1) : "memory");
        }
    }
    CP_WAIT0();
    __syncthreads();

    float acc[4][4][4];
    #pragma unroll
    for (int i = 0; i < 4; i++)
        #pragma unroll
        for (int j = 0; j < 4; j++)
            #pragma unroll
            for (int q = 0; q < 4; q++) acc[i][j][q] = 0.0f;

    const uint32_t aT = smb;
    const uint32_t bT = smb + STILE;
    #pragma unroll
    for (int ks = 0; ks < 4; ks++) {
        const int kb = ks * 32;
        uint32_t af[4][4];
        #pragma unroll
        for (int mi = 0; mi < 4; mi++) {
            const uint32_t addr = aT + (uint32_t)(wr * 64 + mi * 16 + (lane & 15)) * SROW_B
                                  + kb + ((lane >> 4) << 4);
            LDMX4(af[mi], addr);
        }
        uint32_t bf[2][4];
        #pragma unroll
        for (int nj = 0; nj < 2; nj++) {
            const uint32_t addr = bT + (uint32_t)(wc * 32 + nj * 16 + (lane & 15)) * SROW_B
                                  + kb + ((lane >> 4) << 4);
            LDMX4(bf[nj], addr);
        }
        #pragma unroll
        for (int mi = 0; mi < 4; mi++)
            #pragma unroll
            for (int ni = 0; ni < 4; ni++)
                MMA_F16(acc[mi][ni], af[mi], bf[ni >> 1][ni & 1], bf[ni >> 1][(ni & 1) + 2]);
    }

    // epilogue: h = y + (D+1)*x -> fp16
    #pragma unroll
    for (int ni = 0; ni < 4; ni++) {
        const int c = colBase + wc * 32 + ni * 8 + (lane & 3) * 2;
        const float d0 = Dv[c] + 1.0f, d1 = Dv[c + 1] + 1.0f;
        #pragma unroll
        for (int mi = 0; mi < 4; mi++) {
            const int r0 = rowBase + wr * 64 + mi * 16 + (lane >> 2);
            float2 xv0 = *(const float2*)&x[(size_t)r0 * H_ + c];
            float2 xv1 = *(const float2*)&x[(size_t)(r0 + 8) * H_ + c];
            float h00 = fmaf(d0, xv0.x, acc[mi][ni][0]);
            float h01 = fmaf(d1, xv0.y, acc[mi][ni][1]);
            float h10 = fmaf(d0, xv1.x, acc[mi][ni][2]);
            float h11 = fmaf(d1, xv1.y, acc[mi][ni][3]);
            *(__half2*)&g_h[(size_t)r0 * H_ + c]       = __halves2half2(__float2half_rn(h00), __float2half_rn(h01));
            *(__half2*)&g_h[(size_t)(r0 + 8) * H_ + c] = __halves2half2(__float2half_rn(h10), __float2half_rn(h11));
        }
    }
}

// ============================================================
// lnK: row LayerNorm over fp16 h -> fp16 hn. 4 rows/block, 256 thr.
// ============================================================
__global__ void __launch_bounds__(256) lnK(const float* __restrict__ gamma,
                                           const float* __restrict__ beta) {
    __shared__ float redS[8][4], redQ[8][4];
    __shared__ float muA[4], invA[4];
    const int tid = threadIdx.x;
    const int lane = tid & 31, w = tid >> 5;
    const int rowBase = blockIdx.x * 4;
    const int c0 = tid * 4;

    float hv[4][4];
    #pragma unroll
    for (int r = 0; r < 4; r++) {
        __half2 a = *(const __half2*)&g_h[(size_t)(rowBase + r) * H_ + c0];
        __half2 b = *(const __half2*)&g_h[(size_t)(rowBase + r) * H_ + c0 + 2];
        float2 fa = __half22float2(a), fb = __half22float2(b);
        hv[r][0] = fa.x; hv[r][1] = fa.y; hv[r][2] = fb.x; hv[r][3] = fb.y;
        float sm = fa.x + fa.y + fb.x + fb.y;
        float sq = fmaf(fa.x, fa.x, fmaf(fa.y, fa.y, fmaf(fb.x, fb.x, fb.y * fb.y)));
        #pragma unroll
        for (int o = 16; o > 0; o >>= 1) {
            sm += __shfl_down_sync(0xffffffffu, sm, o);
            sq += __shfl_down_sync(0xffffffffu, sq, o);
        }
        if (lane == 0) { redS[w][r] = sm; redQ[w][r] = sq; }
    }
    __syncthreads();
    if (tid < 4) {
        float s = 0.0f, q = 0.0f;
        #pragma unroll
        for (int i = 0; i < 8; i++) { s += redS[i][tid]; q += redQ[i][tid]; }
        float mu = s * (1.0f / H_);
        float var = q * (1.0f / H_) - mu * mu;
        muA[tid] = mu;
        invA[tid] = rsqrtf(var + LN_EPSF);
    }
    __syncthreads();

    float4 gv = *(const float4*)&gamma[c0];
    float4 bv = *(const float4*)&beta[c0];
    #pragma unroll
    for (int r = 0; r < 4; r++) {
        const float mu = muA[r], inv = invA[r];
        float v0 = fmaf((hv[r][0] - mu) * inv, gv.x, bv.x);
        float v1 = fmaf((hv[r][1] - mu) * inv, gv.y, bv.y);
        float v2 = fmaf((hv[r][2] - mu) * inv, gv.z, bv.z);
        float v3 = fmaf((hv[r][3] - mu) * inv, gv.w, bv.w);
        const size_t off = (size_t)(rowBase + r) * H_ + c0;
        *(__half2*)&g_hn_hi[off]     = __halves2half2(__float2half_rn(v0), __float2half_rn(v1));
        *(__half2*)&g_hn_hi[off + 2] = __halves2half2(__float2half_rn(v2), __float2half_rn(v3));
    }
}

// ============================================================
// Kernel D: out = hn_hi @ wo_hi^T + bout, fp16 MMA (K = 1024)
// ============================================================
__global__ void __launch_bounds__(256, 2) outGemmMMA(const float* __restrict__ bout,
                                                     float* __restrict__ out) {
    extern __shared__ char sm[];
    const uint32_t smb = smem_u32(sm);
    const int tid = threadIdx.x;
    const int lane = tid & 31, w = tid >> 5;
    const int wr = w >> 2, wc = w & 3;
    const int rowBase = blockIdx.x * 128;
    const int colBase = blockIdx.y * 128;

    auto loadStage = [&](int stage, int it) {
        const int k0  = it * KT;
        const uint32_t aB = smb + stage * 2 * STILE;
        const uint32_t bB = aB + STILE;
        #pragma unroll
        for (int t = 0; t < 4; t++) {
            const int c = tid + t * 256;
            const int r = c >> 3, j = c & 7;
            CP_ASYNC16(aB + r * SROW_B + j * 16, &g_hn_hi[(size_t)(rowBase + r) * H_ + k0 + j * 8]);
            CP_ASYNC16(bB + r * SROW_B + j * 16, &g_wo_hi[(size_t)(colBase + r) * H_ + k0 + j * 8]);
        }
        CP_COMMIT();
    };

    float acc[4][4][4];
    #pragma unroll
    for (int i = 0; i < 4; i++)
        #pragma unroll
        for (int j = 0; j < 4; j++)
            #pragma unroll
            for (int q = 0; q < 4; q++) acc[i][j][q] = 0.0f;

    loadStage(0, 0);
    const int NIT = 16;
    for (int it = 0; it < NIT; it++) {
        const int stage = it & 1;
        CP_WAIT0();
        __syncthreads();
        if (it + 1 < NIT) loadStage(stage ^ 1, it + 1);
        const uint32_t aT = smb + stage * 2 * STILE;
        const uint32_t bT = aT + STILE;
        #pragma unroll
        for (int ks = 0; ks < 4; ks++) {
            const int kb = ks * 32;
            uint32_t af[4][4];
            #pragma unroll
            for (int mi = 0; mi < 4; mi++) {
                const uint32_t addr = aT + (uint32_t)(wr * 64 + mi * 16 + (lane & 15)) * SROW_B
                                      + kb + ((lane >> 4) << 4);
                LDMX4(af[mi], addr);
            }
            uint32_t bf[2][4];
            #pragma unroll
            for (int nj = 0; nj < 2; nj++) {
                const uint32_t addr = bT + (uint32_t)(wc * 32 + nj * 16 + (lane & 15)) * SROW_B
                                      + kb + ((lane >> 4) << 4);
                LDMX4(bf[nj], addr);
            }
            #pragma unroll
            for (int mi = 0; mi < 4; mi++)
                #pragma unroll
                for (int ni = 0; ni < 4; ni++)
                    MMA_F16(acc[mi][ni], af[mi], bf[ni >> 1][ni & 1], bf[ni >> 1][(ni & 1) + 2]);
        }
        __syncthreads();
    }

    #pragma unroll
    for (int mi = 0; mi < 4; mi++) {
        const int r0 = rowBase + wr * 64 + mi * 16 + (lane >> 2);
        #pragma unroll
        for (int ni = 0; ni < 4; ni++) {
            const int c = colBase + wc * 32 + ni * 8 + (lane & 3) * 2;
            const float b0c = bout[c], b1c = bout[c + 1];
            float2 v0 = make_float2(acc[mi][ni][0] + b0c, acc[mi][ni][1] + b1c);
            float2 v1 = make_float2(acc[mi][ni][2] + b0c, acc[mi][ni][3] + b1c);
            *(float2*)&out[(size_t)r0 * H_ + c]       = v0;
            *(float2*)&out[(size_t)(r0 + 8) * H_ + c] = v1;
        }
    }
}

// ============================================================
// launch
// ============================================================
extern "C" void kernel_launch(void* const* d_in, const int* in_sizes, int n_in,
                              void* d_out, int out_size) {
    const float* x     = (const float*)d_in[0];
    const float* A_log = (const float*)d_in[1];
    const float* WB    = (const float*)d_in[2];
    const float* WC    = (const float*)d_in[3];
    const float* Dv    = (const float*)d_in[4];
    const float* Wg    = (const float*)d_in[5];
    const float* bg    = (const float*)d_in[6];
    const float* Wout  = (const float*)d_in[7];
    const float* bout  = (const float*)d_in[8];
    const float* gamma = (const float*)d_in[9];
    const float* beta  = (const float*)d_in[10];

    float* out = (float*)d_out;
    float* finalState = (out_size >= M_ * H_ + B_ * S_) ? out + (size_t)M_ * H_ : nullptr;

    cudaFuncSetAttribute(outGemmMMA, cudaFuncAttributeMaxDynamicSharedMemorySize, SMEM_D);
    cudaFuncSetAttribute(uGemmMMA,   cudaFuncAttributeMaxDynamicSharedMemorySize, U_SMEM);
    cudaFuncSetAttribute(yGemmMMA,   cudaFuncAttributeMaxDynamicSharedMemorySize, Y_SMEM);

    prepAll<<<1217, 256>>>(Wout, Wg, WB, WC, A_log);
    uGemmMMA<<<M_/64, 256, U_SMEM>>>(x, A_log, bg);
    scanCarry<<<1, B_*S_>>>(A_log, finalState);
    dim3 gY(M_/128, H_/128);
    yGemmMMA<<<gY, 256, Y_SMEM>>>(x, Dv);
    lnK<<<M_/4, 256>>>(gamma, beta);
    dim3 gD(M_/128, H_/128);
    outGemmMMA<<<gD, 256, SMEM_D>>>(bout, out);
}

// round 16
// speedup vs baseline: 1.8057x; 1.0681x over previous
#include <cuda_runtime.h>
#include <cuda_bf16.h>
#include <cuda_fp16.h>
#include <math.h>
#include <stdint.h>

#define B_   4
#define T_   4096
#define H_   1024
#define S_   64
#define M_   (B_*T_)     // 16384 rows
#define NCH  64
#define TC   64
#define LN_EPSF 1e-5f

// ---- scratch ----
__device__ float g_L[B_*NCH*S_];
__device__ float g_E[B_*NCH*S_];
__device__ float g_aPow[TC*S_];
__device__ float g_states[M_*S_];                  // LOCAL states
__device__ __half g_hn_hi[(size_t)M_*H_];          // 32 MB
__device__ __half g_wo_hi[(size_t)H_*H_];          // 2 MB
__device__ __half g_wgb_h[128*H_];
__device__ __half g_wc_h[H_*S_];                   // WC fp16, 128 KB

// ============================================================
// PTX helpers
// ============================================================
__device__ __forceinline__ uint32_t smem_u32(const void* p) {
    uint32_t a;
    asm("{ .reg .u64 t; cvta.to.shared.u64 t, %1; cvt.u32.u64 %0, t; }" : "=r"(a) : "l"(p));
    return a;
}
#define CP_ASYNC16(dst, src) \
    asm volatile("cp.async.cg.shared.global [%0], [%1], 16;" :: "r"(dst), "l"(src) : "memory")
#define CP_COMMIT() asm volatile("cp.async.commit_group;" ::: "memory")
#define CP_WAIT0()  asm volatile("cp.async.wait_group 0;" ::: "memory")

#define LDMX4(r, addr) \
    asm volatile("ldmatrix.sync.aligned.m8n8.x4.shared.b16 {%0,%1,%2,%3}, [%4];" \
        : "=r"((r)[0]), "=r"((r)[1]), "=r"((r)[2]), "=r"((r)[3]) : "r"(addr))

#define MMA_F16(c, a, b0v, b1v) \
    asm volatile("mma.sync.aligned.m16n8k16.row.col.f32.f16.f16.f32 " \
        "{%0,%1,%2,%3},{%4,%5,%6,%7},{%8,%9},{%0,%1,%2,%3};" \
        : "+f"((c)[0]), "+f"((c)[1]), "+f"((c)[2]), "+f"((c)[3]) \
        : "r"((a)[0]), "r"((a)[1]), "r"((a)[2]), "r"((a)[3]), "r"(b0v), "r"(b1v))

// ============================================================
// prepAll: Wout fp16, Wg/WB interleave fp16, WC fp16, aPow.
// ============================================================
__global__ void __launch_bounds__(256) prepAll(const float* __restrict__ Wout,
                                               const float* __restrict__ Wg,
                                               const float* __restrict__ WB,
                                               const float* __restrict__ WC,
                                               const float* __restrict__ A_log) {
    const int bid = blockIdx.x;
    const int tid = threadIdx.x;
    if (bid < 1024) {
        const int base = (bid * 256 + tid) * 4;
        #pragma unroll
        for (int t = 0; t < 4; t++)
            g_wo_hi[base + t] = __float2half_rn(Wout[base + t]);
    } else if (bid < 1152) {
        const int r = bid - 1024;
        const int s = r >> 1;
        const float* src = (r & 1) ? &WB[(size_t)s * H_] : &Wg[(size_t)s * H_];
        for (int k = tid * 4; k < H_; k += 1024) {
            #pragma unroll
            for (int t = 0; t < 4; t++)
                g_wgb_h[(size_t)r * H_ + k + t] = __float2half_rn(src[k + t]);
        }
    } else if (bid < 1216) {
        const int base = ((bid - 1152) * 256 + tid) * 4;
        #pragma unroll
        for (int t = 0; t < 4; t++)
            g_wc_h[base + t] = __float2half_rn(WC[base + t]);
    } else {
        if (tid < S_) {
            const float a = expf(A_log[tid]);
            float pw = 1.0f;
            for (int i = 0; i < TC; i++) {
                pw *= a;
                g_aPow[i * S_ + tid] = pw;
            }
        }
    }
}

// ============================================================
// GEMM geometry
// ============================================================
#define KT     64
#define SROW_B 144           // bytes per smem row (72 x b16)
#define STILE  (128*SROW_B)  // 18432
#define SMEM_D (4*STILE)     // 73728

// ============================================================
// Kernel A: fused uGemm + local scan (proven).
// ============================================================
#define UA_TILE (64*SROW_B)
#define UB_OFF  UA_TILE
#define U_SMEM  (UA_TILE + 2*128*SROW_B)
#define SU_STRIDE 68

__global__ void __launch_bounds__(256, 2) uGemmMMA(const float* __restrict__ x,
                                                   const float* __restrict__ A_log,
                                                   const float* __restrict__ bg) {
    extern __shared__ char sm[];
    const uint32_t smb = smem_u32(sm);
    float* su = (float*)sm;
    const int tid = threadIdx.x;
    const int lane = tid & 31, w = tid >> 5;
    const int wr = w >> 2, wc = w & 3;
    const int rowBase = blockIdx.x * 64;

    const int ar = tid >> 2;
    const int ac = (tid & 3) * 16;
    const float* xrow = &x[(size_t)(rowBase + ar) * H_ + ac];

    auto loadB = [&](int stage, int it) {
        const int k0 = it * KT;
        const uint32_t bB = smb + UB_OFF + stage * (128 * SROW_B);
        #pragma unroll
        for (int t = 0; t < 4; t++) {
            const int c = tid + t * 256;
            const int r = c >> 3, j = c & 7;
            CP_ASYNC16(bB + r * SROW_B + j * 16, &g_wgb_h[(size_t)r * H_ + k0 + j * 8]);
        }
        CP_COMMIT();
    };

    float4 aReg[4];
    #pragma unroll
    for (int q = 0; q < 4; q++) aReg[q] = *(const float4*)&xrow[0 * KT + q * 4];

    float acc[2][4][4];
    #pragma unroll
    for (int i = 0; i < 2; i++)
        #pragma unroll
        for (int j = 0; j < 4; j++)
            #pragma unroll
            for (int q = 0; q < 4; q++) acc[i][j][q] = 0.0f;

    loadB(0, 0);
    const int NIT = 16;
    for (int it = 0; it < NIT; it++) {
        const int stage = it & 1;
        CP_WAIT0();
        __syncthreads();
        {
            const uint32_t aAddr = smb + (uint32_t)ar * SROW_B + ac * 2;
            #pragma unroll
            for (int q = 0; q < 4; q++) {
                __half2 h0 = __halves2half2(__float2half_rn(aReg[q].x), __float2half_rn(aReg[q].y));
                __half2 h1 = __halves2half2(__float2half_rn(aReg[q].z), __float2half_rn(aReg[q].w));
                uint32_t u0 = *(uint32_t*)&h0, u1 = *(uint32_t*)&h1;
                asm volatile("st.shared.v2.u32 [%0], {%1, %2};"
                             :: "r"(aAddr + q * 8), "r"(u0), "r"(u1) : "memory");
            }
        }
        if (it + 1 < NIT) {
            loadB(stage ^ 1, it + 1);
            #pragma unroll
            for (int q = 0; q < 4; q++)
                aReg[q] = *(const float4*)&xrow[(it + 1) * KT + q * 4];
        }
        __syncthreads();

        const uint32_t aT = smb;
        const uint32_t bT = smb + UB_OFF + stage * (128 * SROW_B);
        #pragma unroll
        for (int ks = 0; ks < 4; ks++) {
            const int kb = ks * 32;
            uint32_t af[2][4];
            #pragma unroll
            for (int mi = 0; mi < 2; mi++) {
                const uint32_t addr = aT + (uint32_t)(wr * 32 + mi * 16 + (lane & 15)) * SROW_B
                                      + kb + ((lane >> 4) << 4);
                LDMX4(af[mi], addr);
            }
            uint32_t bf[2][4];
            #pragma unroll
            for (int nj = 0; nj < 2; nj++) {
                const uint32_t addr = bT + (uint32_t)(wc * 32 + nj * 16 + (lane & 15)) * SROW_B
                                      + kb + ((lane >> 4) << 4);
                LDMX4(bf[nj], addr);
            }
            #pragma unroll
            for (int mi = 0; mi < 2; mi++)
                #pragma unroll
                for (int ni = 0; ni < 4; ni++)
                    MMA_F16(acc[mi][ni], af[mi], bf[ni >> 1][ni & 1], bf[ni >> 1][(ni & 1) + 2]);
        }
        __syncthreads();
    }

    #pragma unroll
    for (int mi = 0; mi < 2; mi++) {
        const int lr = wr * 32 + mi * 16 + (lane >> 2);
        #pragma unroll
        for (int ni = 0; ni < 4; ni++) {
            const int c = wc * 32 + ni * 8 + (lane & 3) * 2;
            const int s = c >> 1;
            const float bgs = bg[s];
            float gate0 = 1.0f / (1.0f + expf(-(acc[mi][ni][0] + bgs)));
            float gate1 = 1.0f / (1.0f + expf(-(acc[mi][ni][2] + bgs)));
            su[lr * SU_STRIDE + s]       = gate0 * acc[mi][ni][1];
            su[(lr + 8) * SU_STRIDE + s] = gate1 * acc[mi][ni][3];
        }
    }
    __syncthreads();

    if (tid < S_) {
        const int s = tid;
        const float a = expf(A_log[s]);
        float st = 0.0f;
        #pragma unroll 8
        for (int i = 0; i < TC; i++) {
            st = fmaf(a, st, su[i * SU_STRIDE + s]);
            su[i * SU_STRIDE + s] = st;
        }
        const int b = rowBase >> 12;
        const int c = (rowBase >> 6) & 63;
        g_L[((size_t)b * NCH + c) * S_ + s] = st;
    }
    __syncthreads();

    {
        const int row = tid >> 2, s0 = (tid & 3) * 16;
        #pragma unroll
        for (int q = 0; q < 4; q++) {
            float4 v = *(const float4*)&su[row * SU_STRIDE + s0 + q * 4];
            *(float4*)&g_states[(size_t)(rowBase + row) * S_ + s0 + q * 4] = v;
        }
    }
}

// ============================================================
// scanCarry
// ============================================================
__global__ void scanCarry(const float* __restrict__ A_log, float* __restrict__ finalState) {
    const int tid = threadIdx.x;
    const int b = tid / S_, s = tid % S_;
    const float a = expf(A_log[s]);
    float aTC = 1.0f;
    #pragma unroll
    for (int i = 0; i < TC; i++) aTC *= a;
    float L[NCH];
    #pragma unroll
    for (int c = 0; c < NCH; c++)
        L[c] = g_L[((size_t)b * NCH + c) * S_ + s];
    float E = 0.0f;
    #pragma unroll
    for (int c = 0; c < NCH; c++) {
        g_E[((size_t)b * NCH + c) * S_ + s] = E;
        E = fmaf(aTC, E, L[c]);
    }
    if (finalState) finalState[b * S_ + s] = E;
}

// ============================================================
// yLNGemm: fused h = states@WC^T + (D+1)x, LayerNorm, hn fp16.
// CTA: M=32, N=1024 (full row), K=64. 512 threads, warps 2x8.
// B = full WC fp16 in smem (147 KB). LN in-register + smem reduce.
// ============================================================
#define YA_TILE (32*SROW_B)              // 4608
#define YB_OFF  YA_TILE
#define YL_SMEM (YA_TILE + 1024*SROW_B)  // 152064

__global__ void __launch_bounds__(512, 1) yLNGemm(const float* __restrict__ x,
                                                  const float* __restrict__ Dv,
                                                  const float* __restrict__ gamma,
                                                  const float* __restrict__ beta) {
    extern __shared__ char sm[];
    __shared__ float redS[32][8], redQ[32][8];
    __shared__ float muA[32], invA[32];
    const uint32_t smb = smem_u32(sm);
    const int tid = threadIdx.x;
    const int lane = tid & 31, w = tid >> 5;
    const int wr = w >> 3, wc = w & 7;            // 2 x 8 warps; warp tile 16x128
    const int rowBase = blockIdx.x * 32;

    // B: full WC (1024 rows x 128 B) via cp.async
    #pragma unroll
    for (int t = 0; t < 16; t++) {
        const int c = tid + t * 512;              // 0..8191
        const int r = c >> 3, j = c & 7;
        CP_ASYNC16(smb + YB_OFF + r * SROW_B + j * 16, &g_wc_h[(size_t)r * S_ + j * 8]);
    }
    CP_COMMIT();

    // A: corrected states -> fp16 (512 threads x 4 vals)
    {
        const int r = tid >> 4;                   // 0..31
        const int s0 = (tid & 15) * 4;
        const int grow = rowBase + r;
        const int eRow = grow >> 6;
        const int i = grow & 63;
        float4 loc = *(const float4*)&g_states[(size_t)grow * S_ + s0];
        float4 Ev  = *(const float4*)&g_E[(size_t)eRow * S_ + s0];
        float4 pw  = *(const float4*)&g_aPow[i * S_ + s0];
        float v0 = fmaf(pw.x, Ev.x, loc.x);
        float v1 = fmaf(pw.y, Ev.y, loc.y);
        float v2 = fmaf(pw.z, Ev.z, loc.z);
        float v3 = fmaf(pw.w, Ev.w, loc.w);
        __half2 h0 = __halves2half2(__float2half_rn(v0), __float2half_rn(v1));
        __half2 h1 = __halves2half2(__float2half_rn(v2), __float2half_rn(v3));
        uint32_t u0 = *(uint32_t*)&h0, u1 = *(uint32_t*)&h1;
        asm volatile("st.shared.v2.u32 [%0], {%1, %2};"
                     :: "r"(smb + (uint32_t)r * SROW_B + s0 * 2), "r"(u0), "r"(u1) : "memory");
    }
    CP_WAIT0();
    __syncthreads();

    float acc[16][4];
    #pragma unroll
    for (int ni = 0; ni < 16; ni++)
        #pragma unroll
        for (int q = 0; q < 4; q++) acc[ni][q] = 0.0f;

    #pragma unroll
    for (int ks = 0; ks < 4; ks++) {
        const int kb = ks * 32;
        uint32_t af[4];
        {
            const uint32_t addr = smb + (uint32_t)(wr * 16 + (lane & 15)) * SROW_B
                                  + kb + ((lane >> 4) << 4);
            LDMX4(af, addr);
        }
        uint32_t bf[8][4];
        #pragma unroll
        for (int nj = 0; nj < 8; nj++) {
            const uint32_t addr = smb + YB_OFF
                                  + (uint32_t)(wc * 128 + nj * 16 + (lane & 15)) * SROW_B
                                  + kb + ((lane >> 4) << 4);
            LDMX4(bf[nj], addr);
        }
        #pragma unroll
        for (int ni = 0; ni < 16; ni++)
            MMA_F16(acc[ni], af, bf[ni >> 1][ni & 1], bf[ni >> 1][(ni & 1) + 2]);
    }

    // epilogue: h = y + (D+1)*x, accumulate row sums
    const int gr0 = rowBase + wr * 16 + (lane >> 2);
    float sm0 = 0.f, sq0 = 0.f, sm1 = 0.f, sq1 = 0.f;
    #pragma unroll
    for (int ni = 0; ni < 16; ni++) {
        const int c = wc * 128 + ni * 8 + (lane & 3) * 2;
        const float d0 = Dv[c] + 1.0f, d1 = Dv[c + 1] + 1.0f;
        float2 xv0 = *(const float2*)&x[(size_t)gr0 * H_ + c];
        float2 xv1 = *(const float2*)&x[(size_t)(gr0 + 8) * H_ + c];
        float h00 = fmaf(d0, xv0.x, acc[ni][0]);
        float h01 = fmaf(d1, xv0.y, acc[ni][1]);
        float h10 = fmaf(d0, xv1.x, acc[ni][2]);
        float h11 = fmaf(d1, xv1.y, acc[ni][3]);
        acc[ni][0] = h00; acc[ni][1] = h01; acc[ni][2] = h10; acc[ni][3] = h11;
        sm0 += h00 + h01; sq0 = fmaf(h00, h00, fmaf(h01, h01, sq0));
        sm1 += h10 + h11; sq1 = fmaf(h10, h10, fmaf(h11, h11, sq1));
    }
    // quad reduce (lanes sharing same rows)
    #pragma unroll
    for (int o = 1; o < 4; o <<= 1) {
        sm0 += __shfl_xor_sync(0xffffffffu, sm0, o);
        sq0 += __shfl_xor_sync(0xffffffffu, sq0, o);
        sm1 += __shfl_xor_sync(0xffffffffu, sm1, o);
        sq1 += __shfl_xor_sync(0xffffffffu, sq1, o);
    }
    if ((lane & 3) == 0) {
        const int lr = wr * 16 + (lane >> 2);
        redS[lr][wc] = sm0; redQ[lr][wc] = sq0;
        redS[lr + 8][wc] = sm1; redQ[lr + 8][wc] = sq1;
    }
    __syncthreads();
    if (tid < 32) {
        float s = 0.f, q = 0.f;
        #pragma unroll
        for (int i = 0; i < 8; i++) { s += redS[tid][i]; q += redQ[tid][i]; }
        float mu = s * (1.0f / H_);
        float var = q * (1.0f / H_) - mu * mu;
        muA[tid] = mu;
        invA[tid] = rsqrtf(var + LN_EPSF);
    }
    __syncthreads();

    const int lr0 = wr * 16 + (lane >> 2);
    const float mu0 = muA[lr0], inv0 = invA[lr0];
    const float mu1 = muA[lr0 + 8], inv1 = invA[lr0 + 8];
    #pragma unroll
    for (int ni = 0; ni < 16; ni++) {
        const int c = wc * 128 + ni * 8 + (lane & 3) * 2;
        const float g0 = gamma[c], g1 = gamma[c + 1];
        const float b0 = beta[c],  b1 = beta[c + 1];
        float v00 = fmaf((acc[ni][0] - mu0) * inv0, g0, b0);
        float v01 = fmaf((acc[ni][1] - mu0) * inv0, g1, b1);
        float v10 = fmaf((acc[ni][2] - mu1) * inv1, g0, b0);
        float v11 = fmaf((acc[ni][3] - mu1) * inv1, g1, b1);
        *(__half2*)&g_hn_hi[(size_t)gr0 * H_ + c]       = __halves2half2(__float2half_rn(v00), __float2half_rn(v01));
        *(__half2*)&g_hn_hi[(size_t)(gr0 + 8) * H_ + c] = __halves2half2(__float2half_rn(v10), __float2half_rn(v11));
    }
}

// ============================================================
// Kernel D: out = hn_hi @ wo_hi^T + bout, fp16 MMA (K = 1024)
// ============================================================
__global__ void __launch_bounds__(256, 2) outGemmMMA(const float* __restrict__ bout,
                                                     float* __restrict__ out) {
    extern __shared__ char sm[];
    const uint32_t smb = smem_u32(sm);
    const int tid = threadIdx.x;
    const int lane = tid & 31, w = tid >> 5;
    const int wr = w >> 2, wc = w & 3;
    const int rowBase = blockIdx.x * 128;
    const int colBase = blockIdx.y * 128;

    auto loadStage = [&](int stage, int it) {
        const int k0  = it * KT;
        const uint32_t aB = smb + stage * 2 * STILE;
        const uint32_t bB = aB + STILE;
        #pragma unroll
        for (int t = 0; t < 4; t++) {
            const int c = tid + t * 256;
            const int r = c >> 3, j = c & 7;
            CP_ASYNC16(aB + r * SROW_B + j * 16, &g_hn_hi[(size_t)(rowBase + r) * H_ + k0 + j * 8]);
            CP_ASYNC16(bB + r * SROW_B + j * 16, &g_wo_hi[(size_t)(colBase + r) * H_ + k0 + j * 8]);
        }
        CP_COMMIT();
    };

    float acc[4][4][4];
    #pragma unroll
    for (int i = 0; i < 4; i++)
        #pragma unroll
        for (int j = 0; j < 4; j++)
            #pragma unroll
            for (int q = 0; q < 4; q++) acc[i][j][q] = 0.0f;

    loadStage(0, 0);
    const int NIT = 16;
    for (int it = 0; it < NIT; it++) {
        const int stage = it & 1;
        CP_WAIT0();
        __syncthreads();
        if (it + 1 < NIT) loadStage(stage ^ 1, it + 1);
        const uint32_t aT = smb + stage * 2 * STILE;
        const uint32_t bT = aT + STILE;
        #pragma unroll
        for (int ks = 0; ks < 4; ks++) {
            const int kb = ks * 32;
            uint32_t af[4][4];
            #pragma unroll
            for (int mi = 0; mi < 4; mi++) {
                const uint32_t addr = aT + (uint32_t)(wr * 64 + mi * 16 + (lane & 15)) * SROW_B
                                      + kb + ((lane >> 4) << 4);
                LDMX4(af[mi], addr);
            }
            uint32_t bf[2][4];
            #pragma unroll
            for (int nj = 0; nj < 2; nj++) {
                const uint32_t addr = bT + (uint32_t)(wc * 32 + nj * 16 + (lane & 15)) * SROW_B
                                      + kb + ((lane >> 4) << 4);
                LDMX4(bf[nj], addr);
            }
            #pragma unroll
            for (int mi = 0; mi < 4; mi++)
                #pragma unroll
                for (int ni = 0; ni < 4; ni++)
                    MMA_F16(acc[mi][ni], af[mi], bf[ni >> 1][ni & 1], bf[ni >> 1][(ni & 1) + 2]);
        }
        __syncthreads();
    }

    #pragma unroll
    for (int mi = 0; mi < 4; mi++) {
        const int r0 = rowBase + wr * 64 + mi * 16 + (lane >> 2);
        #pragma unroll
        for (int ni = 0; ni < 4; ni++) {
            const int c = colBase + wc * 32 + ni * 8 + (lane & 3) * 2;
            const float b0c = bout[c], b1c = bout[c + 1];
            float2 v0 = make_float2(acc[mi][ni][0] + b0c, acc[mi][ni][1] + b1c);
            float2 v1 = make_float2(acc[mi][ni][2] + b0c, acc[mi][ni][3] + b1c);
            *(float2*)&out[(size_t)r0 * H_ + c]       = v0;
            *(float2*)&out[(size_t)(r0 + 8) * H_ + c] = v1;
        }
    }
}

// ============================================================
// launch
// ============================================================
extern "C" void kernel_launch(void* const* d_in, const int* in_sizes, int n_in,
                              void* d_out, int out_size) {
    const float* x     = (const float*)d_in[0];
    const float* A_log = (const float*)d_in[1];
    const float* WB    = (const float*)d_in[2];
    const float* WC    = (const float*)d_in[3];
    const float* Dv    = (const float*)d_in[4];
    const float* Wg    = (const float*)d_in[5];
    const float* bg    = (const float*)d_in[6];
    const float* Wout  = (const float*)d_in[7];
    const float* bout  = (const float*)d_in[8];
    const float* gamma = (const float*)d_in[9];
    const float* beta  = (const float*)d_in[10];

    float* out = (float*)d_out;
    float* finalState = (out_size >= M_ * H_ + B_ * S_) ? out + (size_t)M_ * H_ : nullptr;

    cudaFuncSetAttribute(outGemmMMA, cudaFuncAttributeMaxDynamicSharedMemorySize, SMEM_D);
    cudaFuncSetAttribute(uGemmMMA,   cudaFuncAttributeMaxDynamicSharedMemorySize, U_SMEM);
    cudaFuncSetAttribute(yLNGemm,    cudaFuncAttributeMaxDynamicSharedMemorySize, YL_SMEM);

    prepAll<<<1217, 256>>>(Wout, Wg, WB, WC, A_log);
    uGemmMMA<<<M_/64, 256, U_SMEM>>>(x, A_log, bg);
    scanCarry<<<1, B_*S_>>>(A_log, finalState);
    yLNGemm<<<M_/32, 512, YL_SMEM>>>(x, Dv, gamma, beta);
    dim3 gD(M_/128, H_/128);
    outGemmMMA<<<gD, 256, SMEM_D>>>(bout, out);
}

// round 17
// speedup vs baseline: 1.8414x; 1.0198x over previous
#include <cuda_runtime.h>
#include <cuda_bf16.h>
#include <cuda_fp16.h>
#include <math.h>
#include <stdint.h>

#define B_   4
#define T_   4096
#define H_   1024
#define S_   64
#define M_   (B_*T_)     // 16384 rows
#define NCH  64
#define TC   64
#define LN_EPSF 1e-5f

// ---- scratch ----
__device__ float g_L[B_*NCH*S_];
__device__ float g_E[B_*NCH*S_];
__device__ float g_aPow[TC*S_];
__device__ float g_states[M_*S_];                  // LOCAL states
__device__ __half g_hn_hi[(size_t)M_*H_];          // 32 MB
__device__ __half g_wo_hi[(size_t)H_*H_];          // 2 MB
__device__ __half g_wgb_h[128*H_];
__device__ __half g_wc_h[H_*S_];                   // WC fp16, 128 KB

// ============================================================
// PTX helpers
// ============================================================
__device__ __forceinline__ uint32_t smem_u32(const void* p) {
    uint32_t a;
    asm("{ .reg .u64 t; cvta.to.shared.u64 t, %1; cvt.u32.u64 %0, t; }" : "=r"(a) : "l"(p));
    return a;
}
#define CP_ASYNC16(dst, src) \
    asm volatile("cp.async.cg.shared.global [%0], [%1], 16;" :: "r"(dst), "l"(src) : "memory")
#define CP_COMMIT() asm volatile("cp.async.commit_group;" ::: "memory")
#define CP_WAIT0()  asm volatile("cp.async.wait_group 0;" ::: "memory")

#define LDMX4(r, addr) \
    asm volatile("ldmatrix.sync.aligned.m8n8.x4.shared.b16 {%0,%1,%2,%3}, [%4];" \
        : "=r"((r)[0]), "=r"((r)[1]), "=r"((r)[2]), "=r"((r)[3]) : "r"(addr))

#define MMA_F16(c, a, b0v, b1v) \
    asm volatile("mma.sync.aligned.m16n8k16.row.col.f32.f16.f16.f32 " \
        "{%0,%1,%2,%3},{%4,%5,%6,%7},{%8,%9},{%0,%1,%2,%3};" \
        : "+f"((c)[0]), "+f"((c)[1]), "+f"((c)[2]), "+f"((c)[3]) \
        : "r"((a)[0]), "r"((a)[1]), "r"((a)[2]), "r"((a)[3]), "r"(b0v), "r"(b1v))

// ============================================================
// prepAll: Wout fp16, Wg/WB interleave fp16, WC fp16, aPow.
// ============================================================
__global__ void __launch_bounds__(256) prepAll(const float* __restrict__ Wout,
                                               const float* __restrict__ Wg,
                                               const float* __restrict__ WB,
                                               const float* __restrict__ WC,
                                               const float* __restrict__ A_log) {
    const int bid = blockIdx.x;
    const int tid = threadIdx.x;
    if (bid < 1024) {
        const int base = (bid * 256 + tid) * 4;
        #pragma unroll
        for (int t = 0; t < 4; t++)
            g_wo_hi[base + t] = __float2half_rn(Wout[base + t]);
    } else if (bid < 1152) {
        const int r = bid - 1024;
        const int s = r >> 1;
        const float* src = (r & 1) ? &WB[(size_t)s * H_] : &Wg[(size_t)s * H_];
        for (int k = tid * 4; k < H_; k += 1024) {
            #pragma unroll
            for (int t = 0; t < 4; t++)
                g_wgb_h[(size_t)r * H_ + k + t] = __float2half_rn(src[k + t]);
        }
    } else if (bid < 1216) {
        const int base = ((bid - 1152) * 256 + tid) * 4;
        #pragma unroll
        for (int t = 0; t < 4; t++)
            g_wc_h[base + t] = __float2half_rn(WC[base + t]);
    } else {
        if (tid < S_) {
            const float a = expf(A_log[tid]);
            float pw = 1.0f;
            for (int i = 0; i < TC; i++) {
                pw *= a;
                g_aPow[i * S_ + tid] = pw;
            }
        }
    }
}

// ============================================================
// GEMM geometry
// ============================================================
#define KT     64
#define SROW_B 144           // bytes per smem row (72 x b16)
#define STILE  (128*SROW_B)  // 18432
#define SMEM_D (4*STILE)     // 73728

// ============================================================
// Kernel A: fused uGemm + local scan (proven).
// ============================================================
#define UA_TILE (64*SROW_B)
#define UB_OFF  UA_TILE
#define U_SMEM  (UA_TILE + 2*128*SROW_B)
#define SU_STRIDE 68

__global__ void __launch_bounds__(256, 2) uGemmMMA(const float* __restrict__ x,
                                                   const float* __restrict__ A_log,
                                                   const float* __restrict__ bg) {
    extern __shared__ char sm[];
    const uint32_t smb = smem_u32(sm);
    float* su = (float*)sm;
    const int tid = threadIdx.x;
    const int lane = tid & 31, w = tid >> 5;
    const int wr = w >> 2, wc = w & 3;
    const int rowBase = blockIdx.x * 64;

    const int ar = tid >> 2;
    const int ac = (tid & 3) * 16;
    const float* xrow = &x[(size_t)(rowBase + ar) * H_ + ac];

    auto loadB = [&](int stage, int it) {
        const int k0 = it * KT;
        const uint32_t bB = smb + UB_OFF + stage * (128 * SROW_B);
        #pragma unroll
        for (int t = 0; t < 4; t++) {
            const int c = tid + t * 256;
            const int r = c >> 3, j = c & 7;
            CP_ASYNC16(bB + r * SROW_B + j * 16, &g_wgb_h[(size_t)r * H_ + k0 + j * 8]);
        }
        CP_COMMIT();
    };

    float4 aReg[4];
    #pragma unroll
    for (int q = 0; q < 4; q++) aReg[q] = *(const float4*)&xrow[0 * KT + q * 4];

    float acc[2][4][4];
    #pragma unroll
    for (int i = 0; i < 2; i++)
        #pragma unroll
        for (int j = 0; j < 4; j++)
            #pragma unroll
            for (int q = 0; q < 4; q++) acc[i][j][q] = 0.0f;

    loadB(0, 0);
    const int NIT = 16;
    for (int it = 0; it < NIT; it++) {
        const int stage = it & 1;
        CP_WAIT0();
        __syncthreads();
        {
            const uint32_t aAddr = smb + (uint32_t)ar * SROW_B + ac * 2;
            #pragma unroll
            for (int q = 0; q < 4; q++) {
                __half2 h0 = __halves2half2(__float2half_rn(aReg[q].x), __float2half_rn(aReg[q].y));
                __half2 h1 = __halves2half2(__float2half_rn(aReg[q].z), __float2half_rn(aReg[q].w));
                uint32_t u0 = *(uint32_t*)&h0, u1 = *(uint32_t*)&h1;
                asm volatile("st.shared.v2.u32 [%0], {%1, %2};"
                             :: "r"(aAddr + q * 8), "r"(u0), "r"(u1) : "memory");
            }
        }
        if (it + 1 < NIT) {
            loadB(stage ^ 1, it + 1);
            #pragma unroll
            for (int q = 0; q < 4; q++)
                aReg[q] = *(const float4*)&xrow[(it + 1) * KT + q * 4];
        }
        __syncthreads();

        const uint32_t aT = smb;
        const uint32_t bT = smb + UB_OFF + stage * (128 * SROW_B);
        #pragma unroll
        for (int ks = 0; ks < 4; ks++) {
            const int kb = ks * 32;
            uint32_t af[2][4];
            #pragma unroll
            for (int mi = 0; mi < 2; mi++) {
                const uint32_t addr = aT + (uint32_t)(wr * 32 + mi * 16 + (lane & 15)) * SROW_B
                                      + kb + ((lane >> 4) << 4);
                LDMX4(af[mi], addr);
            }
            uint32_t bf[2][4];
            #pragma unroll
            for (int nj = 0; nj < 2; nj++) {
                const uint32_t addr = bT + (uint32_t)(wc * 32 + nj * 16 + (lane & 15)) * SROW_B
                                      + kb + ((lane >> 4) << 4);
                LDMX4(bf[nj], addr);
            }
            #pragma unroll
            for (int mi = 0; mi < 2; mi++)
                #pragma unroll
                for (int ni = 0; ni < 4; ni++)
                    MMA_F16(acc[mi][ni], af[mi], bf[ni >> 1][ni & 1], bf[ni >> 1][(ni & 1) + 2]);
        }
        __syncthreads();
    }

    #pragma unroll
    for (int mi = 0; mi < 2; mi++) {
        const int lr = wr * 32 + mi * 16 + (lane >> 2);
        #pragma unroll
        for (int ni = 0; ni < 4; ni++) {
            const int c = wc * 32 + ni * 8 + (lane & 3) * 2;
            const int s = c >> 1;
            const float bgs = bg[s];
            float gate0 = 1.0f / (1.0f + expf(-(acc[mi][ni][0] + bgs)));
            float gate1 = 1.0f / (1.0f + expf(-(acc[mi][ni][2] + bgs)));
            su[lr * SU_STRIDE + s]       = gate0 * acc[mi][ni][1];
            su[(lr + 8) * SU_STRIDE + s] = gate1 * acc[mi][ni][3];
        }
    }
    __syncthreads();

    if (tid < S_) {
        const int s = tid;
        const float a = expf(A_log[s]);
        float st = 0.0f;
        #pragma unroll 8
        for (int i = 0; i < TC; i++) {
            st = fmaf(a, st, su[i * SU_STRIDE + s]);
            su[i * SU_STRIDE + s] = st;
        }
        const int b = rowBase >> 12;
        const int c = (rowBase >> 6) & 63;
        g_L[((size_t)b * NCH + c) * S_ + s] = st;
    }
    __syncthreads();

    {
        const int row = tid >> 2, s0 = (tid & 3) * 16;
        #pragma unroll
        for (int q = 0; q < 4; q++) {
            float4 v = *(const float4*)&su[row * SU_STRIDE + s0 + q * 4];
            *(float4*)&g_states[(size_t)(rowBase + row) * S_ + s0 + q * 4] = v;
        }
    }
}

// ============================================================
// scanCarry
// ============================================================
__global__ void scanCarry(const float* __restrict__ A_log, float* __restrict__ finalState) {
    const int tid = threadIdx.x;
    const int b = tid / S_, s = tid % S_;
    const float a = expf(A_log[s]);
    float aTC = 1.0f;
    #pragma unroll
    for (int i = 0; i < TC; i++) aTC *= a;
    float L[NCH];
    #pragma unroll
    for (int c = 0; c < NCH; c++)
        L[c] = g_L[((size_t)b * NCH + c) * S_ + s];
    float E = 0.0f;
    #pragma unroll
    for (int c = 0; c < NCH; c++) {
        g_E[((size_t)b * NCH + c) * S_ + s] = E;
        E = fmaf(aTC, E, L[c]);
    }
    if (finalState) finalState[b * S_ + s] = E;
}

// ============================================================
// yLNGemm: PERSISTENT fused h = states@WC^T + (D+1)x, LN, hn fp16.
// grid = NSM CTAs; WC loaded to smem ONCE per CTA; loop over M-tiles.
// CTA tile: M=32, N=1024, K=64. 512 threads, warps 2x8.
// ============================================================
#define YA_TILE (32*SROW_B)              // 4608
#define YB_OFF  YA_TILE
#define YL_SMEM (YA_TILE + 1024*SROW_B)  // 152064
#define NSM 148

__global__ void __launch_bounds__(512, 1) yLNGemm(const float* __restrict__ x,
                                                  const float* __restrict__ Dv,
                                                  const float* __restrict__ gamma,
                                                  const float* __restrict__ beta) {
    extern __shared__ char sm[];
    __shared__ float redS[32][8], redQ[32][8];
    __shared__ float muA[32], invA[32];
    const uint32_t smb = smem_u32(sm);
    const int tid = threadIdx.x;
    const int lane = tid & 31, w = tid >> 5;
    const int wr = w >> 3, wc = w & 7;            // 2 x 8 warps; warp tile 16x128
    const int nTiles = M_ / 32;                   // 512

    // B: full WC (1024 rows x 128 B) once
    #pragma unroll
    for (int t = 0; t < 16; t++) {
        const int c = tid + t * 512;
        const int r = c >> 3, j = c & 7;
        CP_ASYNC16(smb + YB_OFF + r * SROW_B + j * 16, &g_wc_h[(size_t)r * S_ + j * 8]);
    }
    CP_COMMIT();
    CP_WAIT0();

    for (int tile = blockIdx.x; tile < nTiles; tile += gridDim.x) {
        const int rowBase = tile * 32;

        // A: corrected states -> fp16 (512 threads x 4 vals)
        {
            const int r = tid >> 4;
            const int s0 = (tid & 15) * 4;
            const int grow = rowBase + r;
            const int eRow = grow >> 6;
            const int i = grow & 63;
            float4 loc = *(const float4*)&g_states[(size_t)grow * S_ + s0];
            float4 Ev  = *(const float4*)&g_E[(size_t)eRow * S_ + s0];
            float4 pw  = *(const float4*)&g_aPow[i * S_ + s0];
            float v0 = fmaf(pw.x, Ev.x, loc.x);
            float v1 = fmaf(pw.y, Ev.y, loc.y);
            float v2 = fmaf(pw.z, Ev.z, loc.z);
            float v3 = fmaf(pw.w, Ev.w, loc.w);
            __half2 h0 = __halves2half2(__float2half_rn(v0), __float2half_rn(v1));
            __half2 h1 = __halves2half2(__float2half_rn(v2), __float2half_rn(v3));
            uint32_t u0 = *(uint32_t*)&h0, u1 = *(uint32_t*)&h1;
            asm volatile("st.shared.v2.u32 [%0], {%1, %2};"
                         :: "r"(smb + (uint32_t)r * SROW_B + s0 * 2), "r"(u0), "r"(u1) : "memory");
        }
        __syncthreads();

        float acc[16][4];
        #pragma unroll
        for (int ni = 0; ni < 16; ni++)
            #pragma unroll
            for (int q = 0; q < 4; q++) acc[ni][q] = 0.0f;

        #pragma unroll
        for (int ks = 0; ks < 4; ks++) {
            const int kb = ks * 32;
            uint32_t af[4];
            {
                const uint32_t addr = smb + (uint32_t)(wr * 16 + (lane & 15)) * SROW_B
                                      + kb + ((lane >> 4) << 4);
                LDMX4(af, addr);
            }
            uint32_t bf[8][4];
            #pragma unroll
            for (int nj = 0; nj < 8; nj++) {
                const uint32_t addr = smb + YB_OFF
                                      + (uint32_t)(wc * 128 + nj * 16 + (lane & 15)) * SROW_B
                                      + kb + ((lane >> 4) << 4);
                LDMX4(bf[nj], addr);
            }
            #pragma unroll
            for (int ni = 0; ni < 16; ni++)
                MMA_F16(acc[ni], af, bf[ni >> 1][ni & 1], bf[ni >> 1][(ni & 1) + 2]);
        }

        // epilogue: h = y + (D+1)*x, row sums
        const int gr0 = rowBase + wr * 16 + (lane >> 2);
        float sm0 = 0.f, sq0 = 0.f, sm1 = 0.f, sq1 = 0.f;
        #pragma unroll
        for (int ni = 0; ni < 16; ni++) {
            const int c = wc * 128 + ni * 8 + (lane & 3) * 2;
            const float d0 = Dv[c] + 1.0f, d1 = Dv[c + 1] + 1.0f;
            float2 xv0 = *(const float2*)&x[(size_t)gr0 * H_ + c];
            float2 xv1 = *(const float2*)&x[(size_t)(gr0 + 8) * H_ + c];
            float h00 = fmaf(d0, xv0.x, acc[ni][0]);
            float h01 = fmaf(d1, xv0.y, acc[ni][1]);
            float h10 = fmaf(d0, xv1.x, acc[ni][2]);
            float h11 = fmaf(d1, xv1.y, acc[ni][3]);
            acc[ni][0] = h00; acc[ni][1] = h01; acc[ni][2] = h10; acc[ni][3] = h11;
            sm0 += h00 + h01; sq0 = fmaf(h00, h00, fmaf(h01, h01, sq0));
            sm1 += h10 + h11; sq1 = fmaf(h10, h10, fmaf(h11, h11, sq1));
        }
        #pragma unroll
        for (int o = 1; o < 4; o <<= 1) {
            sm0 += __shfl_xor_sync(0xffffffffu, sm0, o);
            sq0 += __shfl_xor_sync(0xffffffffu, sq0, o);
            sm1 += __shfl_xor_sync(0xffffffffu, sm1, o);
            sq1 += __shfl_xor_sync(0xffffffffu, sq1, o);
        }
        if ((lane & 3) == 0) {
            const int lr = wr * 16 + (lane >> 2);
            redS[lr][wc] = sm0; redQ[lr][wc] = sq0;
            redS[lr + 8][wc] = sm1; redQ[lr + 8][wc] = sq1;
        }
        __syncthreads();
        if (tid < 32) {
            float s = 0.f, q = 0.f;
            #pragma unroll
            for (int i = 0; i < 8; i++) { s += redS[tid][i]; q += redQ[tid][i]; }
            float mu = s * (1.0f / H_);
            float var = q * (1.0f / H_) - mu * mu;
            muA[tid] = mu;
            invA[tid] = rsqrtf(var + LN_EPSF);
        }
        __syncthreads();

        const int lr0 = wr * 16 + (lane >> 2);
        const float mu0 = muA[lr0], inv0 = invA[lr0];
        const float mu1 = muA[lr0 + 8], inv1 = invA[lr0 + 8];
        #pragma unroll
        for (int ni = 0; ni < 16; ni++) {
            const int c = wc * 128 + ni * 8 + (lane & 3) * 2;
            const float g0 = gamma[c], g1 = gamma[c + 1];
            const float b0 = beta[c],  b1 = beta[c + 1];
            float v00 = fmaf((acc[ni][0] - mu0) * inv0, g0, b0);
            float v01 = fmaf((acc[ni][1] - mu0) * inv0, g1, b1);
            float v10 = fmaf((acc[ni][2] - mu1) * inv1, g0, b0);
            float v11 = fmaf((acc[ni][3] - mu1) * inv1, g1, b1);
            *(__half2*)&g_hn_hi[(size_t)gr0 * H_ + c]       = __halves2half2(__float2half_rn(v00), __float2half_rn(v01));
            *(__half2*)&g_hn_hi[(size_t)(gr0 + 8) * H_ + c] = __halves2half2(__float2half_rn(v10), __float2half_rn(v11));
        }
        __syncthreads();   // guard A-tile + red arrays before next iteration
    }
}

// ============================================================
// Kernel D: out = hn_hi @ wo_hi^T + bout, fp16 MMA (K = 1024)
// ============================================================
__global__ void __launch_bounds__(256, 2) outGemmMMA(const float* __restrict__ bout,
                                                     float* __restrict__ out) {
    extern __shared__ char sm[];
    const uint32_t smb = smem_u32(sm);
    const int tid = threadIdx.x;
    const int lane = tid & 31, w = tid >> 5;
    const int wr = w >> 2, wc = w & 3;
    const int rowBase = blockIdx.x * 128;
    const int colBase = blockIdx.y * 128;

    auto loadStage = [&](int stage, int it) {
        const int k0  = it * KT;
        const uint32_t aB = smb + stage * 2 * STILE;
        const uint32_t bB = aB + STILE;
        #pragma unroll
        for (int t = 0; t < 4; t++) {
            const int c = tid + t * 256;
            const int r = c >> 3, j = c & 7;
            CP_ASYNC16(aB + r * SROW_B + j * 16, &g_hn_hi[(size_t)(rowBase + r) * H_ + k0 + j * 8]);
            CP_ASYNC16(bB + r * SROW_B + j * 16, &g_wo_hi[(size_t)(colBase + r) * H_ + k0 + j * 8]);
        }
        CP_COMMIT();
    };

    float acc[4][4][4];
    #pragma unroll
    for (int i = 0; i < 4; i++)
        #pragma unroll
        for (int j = 0; j < 4; j++)
            #pragma unroll
            for (int q = 0; q < 4; q++) acc[i][j][q] = 0.0f;

    loadStage(0, 0);
    const int NIT = 16;
    for (int it = 0; it < NIT; it++) {
        const int stage = it & 1;
        CP_WAIT0();
        __syncthreads();
        if (it + 1 < NIT) loadStage(stage ^ 1, it + 1);
        const uint32_t aT = smb + stage * 2 * STILE;
        const uint32_t bT = aT + STILE;
        #pragma unroll
        for (int ks = 0; ks < 4; ks++) {
            const int kb = ks * 32;
            uint32_t af[4][4];
            #pragma unroll
            for (int mi = 0; mi < 4; mi++) {
                const uint32_t addr = aT + (uint32_t)(wr * 64 + mi * 16 + (lane & 15)) * SROW_B
                                      + kb + ((lane >> 4) << 4);
                LDMX4(af[mi], addr);
            }
            uint32_t bf[2][4];
            #pragma unroll
            for (int nj = 0; nj < 2; nj++) {
                const uint32_t addr = bT + (uint32_t)(wc * 32 + nj * 16 + (lane & 15)) * SROW_B
                                      + kb + ((lane >> 4) << 4);
                LDMX4(bf[nj], addr);
            }
            #pragma unroll
            for (int mi = 0; mi < 4; mi++)
                #pragma unroll
                for (int ni = 0; ni < 4; ni++)
                    MMA_F16(acc[mi][ni], af[mi], bf[ni >> 1][ni & 1], bf[ni >> 1][(ni & 1) + 2]);
        }
        __syncthreads();
    }

    #pragma unroll
    for (int mi = 0; mi < 4; mi++) {
        const int r0 = rowBase + wr * 64 + mi * 16 + (lane >> 2);
        #pragma unroll
        for (int ni = 0; ni < 4; ni++) {
            const int c = colBase + wc * 32 + ni * 8 + (lane & 3) * 2;
            const float b0c = bout[c], b1c = bout[c + 1];
            float2 v0 = make_float2(acc[mi][ni][0] + b0c, acc[mi][ni][1] + b1c);
            float2 v1 = make_float2(acc[mi][ni][2] + b0c, acc[mi][ni][3] + b1c);
            *(float2*)&out[(size_t)r0 * H_ + c]       = v0;
            *(float2*)&out[(size_t)(r0 + 8) * H_ + c] = v1;
        }
    }
}

// ============================================================
// launch
// ============================================================
extern "C" void kernel_launch(void* const* d_in, const int* in_sizes, int n_in,
                              void* d_out, int out_size) {
    const float* x     = (const float*)d_in[0];
    const float* A_log = (const float*)d_in[1];
    const float* WB    = (const float*)d_in[2];
    const float* WC    = (const float*)d_in[3];
    const float* Dv    = (const float*)d_in[4];
    const float* Wg    = (const float*)d_in[5];
    const float* bg    = (const float*)d_in[6];
    const float* Wout  = (const float*)d_in[7];
    const float* bout  = (const float*)d_in[8];
    const float* gamma = (const float*)d_in[9];
    const float* beta  = (const float*)d_in[10];

    float* out = (float*)d_out;
    float* finalState = (out_size >= M_ * H_ + B_ * S_) ? out + (size_t)M_ * H_ : nullptr;

    cudaFuncSetAttribute(outGemmMMA, cudaFuncAttributeMaxDynamicSharedMemorySize, SMEM_D);
    cudaFuncSetAttribute(uGemmMMA,   cudaFuncAttributeMaxDynamicSharedMemorySize, U_SMEM);
    cudaFuncSetAttribute(yLNGemm,    cudaFuncAttributeMaxDynamicSharedMemorySize, YL_SMEM);

    prepAll<<<1217, 256>>>(Wout, Wg, WB, WC, A_log);
    uGemmMMA<<<M_/64, 256, U_SMEM>>>(x, A_log, bg);
    scanCarry<<<1, B_*S_>>>(A_log, finalState);
    yLNGemm<<<NSM, 512, YL_SMEM>>>(x, Dv, gamma, beta);
    dim3 gD(M_/128, H_/128);
    outGemmMMA<<<gD, 256, SMEM_D>>>(bout, out);
}